// round 1
// baseline (speedup 1.0000x reference)
#include <cuda_runtime.h>
#include <math.h>

#define HH 96
#define WW 96
#define CC 256
#define FF 256
#define BB 4
#define NPIX (HH*WW)        // 9216
#define TOTPIX (BB*NPIX)    // 36864

// scratch: per (pixel, tap): (py, px, mask, 0)
__device__ float4 g_offmask[TOTPIX * 9];

// ---------------------------------------------------------------------------
// Kernel 1: offset/mask conv (3x3x256 -> 27) for a 16-pixel row tile.
// grid = B * 96 * 6 blocks, 128 threads.
// Thread t: oc = t % 27, s = t / 27 (channel stride group, s<4 active).
// Each thread accumulates its oc for all 16 pixels (weight LDG amortized 16x).
// ---------------------------------------------------------------------------
__global__ void __launch_bounds__(128) om_conv_kernel(
    const float* __restrict__ x, const float* __restrict__ omk,
    const float* __restrict__ omb)
{
    __shared__ float win[3][64][20];   // [row][channel][col(18 used)]
    __shared__ float red[4][16][28];
    __shared__ float om_s[16][27];

    int bi  = blockIdx.x;
    int wch = bi % 6;
    int ho  = (bi / 6) % 96;
    int b   = bi / 576;
    int tid = threadIdx.x;
    int oc  = tid % 27;
    int s   = tid / 27;      // 0..4 (s==4 idle in compute)

    float acc[16];
#pragma unroll
    for (int p = 0; p < 16; ++p) acc[p] = 0.f;

    const float* xb = x + (size_t)b * NPIX * CC;

    for (int cc = 0; cc < 4; ++cc) {
        int c0 = cc * 64;
        // load 3 x 18 x 64 window (zero padded at borders)
        for (int idx = tid; idx < 3456; idx += 128) {
            int ry  = idx / 1152;
            int rem = idx % 1152;
            int cx  = rem / 64;
            int c   = rem % 64;
            int y   = ho - 1 + ry;
            int xx  = wch * 16 - 1 + cx;
            float v = 0.f;
            if (y >= 0 && y < HH && xx >= 0 && xx < WW)
                v = xb[(y * WW + xx) * CC + c0 + c];
            win[ry][c][cx] = v;
        }
        __syncthreads();

        if (s < 4) {
            for (int t9 = 0; t9 < 9; ++t9) {
                int ky = t9 / 3, kx = t9 % 3;
                for (int ci = s; ci < 64; ci += 4) {
                    float w = omk[((t9 * 256) + c0 + ci) * 27 + oc];
                    const float* base = &win[ky][ci][kx];
#pragma unroll
                    for (int p = 0; p < 16; ++p) acc[p] += w * base[p];
                }
            }
        }
        __syncthreads();
    }

    if (s < 4) {
#pragma unroll
        for (int p = 0; p < 16; ++p) red[s][p][oc] = acc[p];
    }
    __syncthreads();

    for (int e = tid; e < 432; e += 128) {
        int pp = e / 27, o = e % 27;
        om_s[pp][o] = red[0][pp][o] + red[1][pp][o] + red[2][pp][o]
                    + red[3][pp][o] + omb[o];
    }
    __syncthreads();

    for (int e = tid; e < 144; e += 128) {
        int pp = e / 9, k = e % 9;
        float dy = om_s[pp][2 * k];
        float dx = om_s[pp][2 * k + 1];
        float m  = 2.f / (1.f + expf(-om_s[pp][18 + k]));
        int ky = k / 3, kx = k % 3;
        int wo = wch * 16 + pp;
        float py = (float)(ho - 1 + ky) + dy;
        float px = (float)(wo - 1 + kx) + dx;
        int pix = b * NPIX + ho * WW + wo;
        g_offmask[pix * 9 + k] = make_float4(py, px, m, 0.f);
    }
}

// ---------------------------------------------------------------------------
// Kernel 2: fused bilinear sampling + GEMM.
// grid = 576 blocks (64 pixels each), 256 threads.
// Output tile: [64 pixels][256 F], 8x8 register micro-tile per thread.
// K loop: 9 taps x 8 chunks of 32 channels; A tile sampled on the fly.
// ---------------------------------------------------------------------------
__global__ void __launch_bounds__(256) dcn_gemm_kernel(
    const float* __restrict__ x, const float* __restrict__ kern,
    const float* __restrict__ bias, float* __restrict__ out)
{
    __shared__ float As[32 * 68];    // [kk][pixel], row padded to 68
    __shared__ float Bs[32 * 256];   // [kk][f]

    int tid   = threadIdx.x;
    int tile0 = blockIdx.x * 64;
    int b     = tile0 / NPIX;
    const float* xb = x + (size_t)b * NPIX * CC;

    // sampler mapping
    int p = tid & 63;       // pixel within tile
    int q = tid >> 6;       // channel quarter (8 channels)
    int pix = tile0 + p;

    // gemm mapping
    int ty = tid >> 5;      // row group (8 rows)
    int tx = tid & 31;      // col group (8 cols)

    float acc[8][8];
#pragma unroll
    for (int i = 0; i < 8; ++i)
#pragma unroll
        for (int j = 0; j < 8; ++j) acc[i][j] = 0.f;

    const float4* kern4 = (const float4*)kern;

    for (int tap = 0; tap < 9; ++tap) {
        // per-tap bilinear setup for this thread's pixel
        float4 om = g_offmask[pix * 9 + tap];
        float fy0 = floorf(om.x), fx0 = floorf(om.y);
        int iy0 = (int)fy0, ix0 = (int)fx0;
        float fy = om.x - fy0, fx = om.y - fx0;
        float m = om.z;
        float w00 = (1.f - fy) * (1.f - fx) * m;
        float w01 = (1.f - fy) * fx * m;
        float w10 = fy * (1.f - fx) * m;
        float w11 = fy * fx * m;
        if (iy0 < 0  || iy0 >= HH)     { w00 = 0.f; w01 = 0.f; }
        if (iy0 < -1 || iy0 >= HH - 1) { w10 = 0.f; w11 = 0.f; }
        if (ix0 < 0  || ix0 >= WW)     { w00 = 0.f; w10 = 0.f; }
        if (ix0 < -1 || ix0 >= WW - 1) { w01 = 0.f; w11 = 0.f; }
        int y0c = min(max(iy0, 0), HH - 1);
        int y1c = min(max(iy0 + 1, 0), HH - 1);
        int x0c = min(max(ix0, 0), WW - 1);
        int x1c = min(max(ix0 + 1, 0), WW - 1);
        const float* p00 = xb + (y0c * WW + x0c) * CC;
        const float* p01 = xb + (y0c * WW + x1c) * CC;
        const float* p10 = xb + (y1c * WW + x0c) * CC;
        const float* p11 = xb + (y1c * WW + x1c) * CC;

        for (int cb8 = 0; cb8 < 8; ++cb8) {
            int kc = tap * 8 + cb8;         // K-chunk index (0..71)
            int c  = cb8 * 32 + q * 8;      // this thread's channel base

            // ---- stage A: bilinear sample 8 channels ----
            float4 t0 = *(const float4*)(p00 + c);
            float4 t1 = *(const float4*)(p00 + c + 4);
            float4 u0 = *(const float4*)(p01 + c);
            float4 u1 = *(const float4*)(p01 + c + 4);
            float4 s0 = *(const float4*)(p10 + c);
            float4 s1 = *(const float4*)(p10 + c + 4);
            float4 r0 = *(const float4*)(p11 + c);
            float4 r1 = *(const float4*)(p11 + c + 4);
            float va[8];
            va[0] = w00*t0.x + w01*u0.x + w10*s0.x + w11*r0.x;
            va[1] = w00*t0.y + w01*u0.y + w10*s0.y + w11*r0.y;
            va[2] = w00*t0.z + w01*u0.z + w10*s0.z + w11*r0.z;
            va[3] = w00*t0.w + w01*u0.w + w10*s0.w + w11*r0.w;
            va[4] = w00*t1.x + w01*u1.x + w10*s1.x + w11*r1.x;
            va[5] = w00*t1.y + w01*u1.y + w10*s1.y + w11*r1.y;
            va[6] = w00*t1.z + w01*u1.z + w10*s1.z + w11*r1.z;
            va[7] = w00*t1.w + w01*u1.w + w10*s1.w + w11*r1.w;

            // ---- stage B: 32 rows x 256 cols of the weight matrix ----
            float4 breg[8];
#pragma unroll
            for (int it = 0; it < 8; ++it)
                breg[it] = kern4[kc * 2048 + tid + it * 256];

            __syncthreads();   // previous chunk fully consumed

#pragma unroll
            for (int j = 0; j < 8; ++j)
                As[(q * 8 + j) * 68 + p] = va[j];
#pragma unroll
            for (int it = 0; it < 8; ++it)
                *(float4*)&Bs[(tid + it * 256) * 4] = breg[it];

            __syncthreads();   // tile visible

            // ---- FMA: 32 x (8x8) ----
#pragma unroll 4
            for (int kk = 0; kk < 32; ++kk) {
                float4 a0 = *(const float4*)&As[kk * 68 + ty * 8];
                float4 a1 = *(const float4*)&As[kk * 68 + ty * 8 + 4];
                float4 b0 = *(const float4*)&Bs[kk * 256 + tx * 8];
                float4 b1 = *(const float4*)&Bs[kk * 256 + tx * 8 + 4];
                float av[8] = {a0.x, a0.y, a0.z, a0.w, a1.x, a1.y, a1.z, a1.w};
                float bv[8] = {b0.x, b0.y, b0.z, b0.w, b1.x, b1.y, b1.z, b1.w};
#pragma unroll
                for (int rr = 0; rr < 8; ++rr)
#pragma unroll
                    for (int j = 0; j < 8; ++j)
                        acc[rr][j] += av[rr] * bv[j];
            }
        }
    }

    // ---- epilogue: bias + store ----
    float bv0[8];
#pragma unroll
    for (int j = 0; j < 8; ++j) bv0[j] = bias[tx * 8 + j];

#pragma unroll
    for (int rr = 0; rr < 8; ++rr) {
        int r = tile0 + ty * 8 + rr;
        float* o = out + (size_t)r * FF + tx * 8;
        float4 o0, o1;
        o0.x = acc[rr][0] + bv0[0];
        o0.y = acc[rr][1] + bv0[1];
        o0.z = acc[rr][2] + bv0[2];
        o0.w = acc[rr][3] + bv0[3];
        o1.x = acc[rr][4] + bv0[4];
        o1.y = acc[rr][5] + bv0[5];
        o1.z = acc[rr][6] + bv0[6];
        o1.w = acc[rr][7] + bv0[7];
        *(float4*)o       = o0;
        *(float4*)(o + 4) = o1;
    }
}

extern "C" void kernel_launch(void* const* d_in, const int* in_sizes, int n_in,
                              void* d_out, int out_size)
{
    const float* x    = (const float*)d_in[0];  // [4,96,96,256]
    const float* omk  = (const float*)d_in[1];  // [3,3,256,27]
    const float* omb  = (const float*)d_in[2];  // [27]
    const float* kern = (const float*)d_in[3];  // [2304,256]
    const float* bias = (const float*)d_in[4];  // [256]
    float* out = (float*)d_out;                 // [4,96,96,256]

    om_conv_kernel<<<BB * 96 * 6, 128>>>(x, omk, omb);
    dcn_gemm_kernel<<<TOTPIX / 64, 256>>>(x, kern, bias, out);
}

// round 3
// speedup vs baseline: 1.7546x; 1.7546x over previous
#include <cuda_runtime.h>
#include <math.h>
#include <stdint.h>

#define HH 96
#define WW 96
#define CC 256
#define FF 256
#define BB 4
#define NPIX (HH*WW)        // 9216
#define TOTPIX (BB*NPIX)    // 36864
#define NCHUNK 72           // 2304 / 32

// scratch: per (pixel, tap): (py, px, mask, 0)
__device__ float4 g_offmask[TOTPIX * 9];
// weights in mma-fragment order: [chunk72][ktp2][ntile32][lane32][4]
__device__ float g_kernB[NCHUNK * 2 * 32 * 32 * 4];

__device__ __forceinline__ float tf32r(float f) {
    float r;
    asm("cvt.rna.tf32.f32 %0, %1;" : "=f"(r) : "f"(f));
    return r;
}

__device__ __forceinline__ void mma_tf32(
    float* d, uint32_t a0, uint32_t a1, uint32_t a2, uint32_t a3,
    uint32_t b0, uint32_t b1)
{
    asm volatile(
        "mma.sync.aligned.m16n8k8.row.col.f32.tf32.tf32.f32 "
        "{%0,%1,%2,%3}, {%4,%5,%6,%7}, {%8,%9}, {%0,%1,%2,%3};"
        : "+f"(d[0]), "+f"(d[1]), "+f"(d[2]), "+f"(d[3])
        : "r"(a0), "r"(a1), "r"(a2), "r"(a3), "r"(b0), "r"(b1));
}

// ---------------------------------------------------------------------------
// Kernel 0: weight shuffle into fragment order (tf32-rounded).
// element j of float4 idx (ch,ktp,nt,t):
//   k = ch*32 + ktp*16 + (t&3) + j*4   (j=0..3 -> b0/b1 of kt even, b0/b1 of kt odd)
//   n = nt*8 + (t>>2)
// ---------------------------------------------------------------------------
__global__ void __launch_bounds__(256) transpose_kernel(const float* __restrict__ kern)
{
    int idx = blockIdx.x * 256 + threadIdx.x;    // 0 .. 147455
    int t   = idx & 31;
    int nt  = (idx >> 5) & 31;
    int ktp = (idx >> 10) & 1;
    int ch  = idx >> 11;
    int n = nt * 8 + (t >> 2);
    int kbase = ch * 32 + ktp * 16 + (t & 3);
    float4 v;
    v.x = tf32r(kern[(kbase + 0)  * 256 + n]);
    v.y = tf32r(kern[(kbase + 4)  * 256 + n]);
    v.z = tf32r(kern[(kbase + 8)  * 256 + n]);
    v.w = tf32r(kern[(kbase + 12) * 256 + n]);
    ((float4*)g_kernB)[idx] = v;
}

// ---------------------------------------------------------------------------
// Kernel 1: offset/mask conv (unchanged, proven correct)
// ---------------------------------------------------------------------------
__global__ void __launch_bounds__(128) om_conv_kernel(
    const float* __restrict__ x, const float* __restrict__ omk,
    const float* __restrict__ omb)
{
    __shared__ float win[3][64][20];
    __shared__ float red[4][16][28];
    __shared__ float om_s[16][27];

    int bi  = blockIdx.x;
    int wch = bi % 6;
    int ho  = (bi / 6) % 96;
    int b   = bi / 576;
    int tid = threadIdx.x;
    int oc  = tid % 27;
    int s   = tid / 27;

    float acc[16];
#pragma unroll
    for (int p = 0; p < 16; ++p) acc[p] = 0.f;

    const float* xb = x + (size_t)b * NPIX * CC;

    for (int cc = 0; cc < 4; ++cc) {
        int c0 = cc * 64;
        for (int idx = tid; idx < 3456; idx += 128) {
            int ry  = idx / 1152;
            int rem = idx % 1152;
            int cx  = rem / 64;
            int c   = rem % 64;
            int y   = ho - 1 + ry;
            int xx  = wch * 16 - 1 + cx;
            float v = 0.f;
            if (y >= 0 && y < HH && xx >= 0 && xx < WW)
                v = xb[(y * WW + xx) * CC + c0 + c];
            win[ry][c][cx] = v;
        }
        __syncthreads();

        if (s < 4) {
            for (int t9 = 0; t9 < 9; ++t9) {
                int ky = t9 / 3, kx = t9 % 3;
                for (int ci = s; ci < 64; ci += 4) {
                    float w = omk[((t9 * 256) + c0 + ci) * 27 + oc];
                    const float* base = &win[ky][ci][kx];
#pragma unroll
                    for (int p = 0; p < 16; ++p) acc[p] += w * base[p];
                }
            }
        }
        __syncthreads();
    }

    if (s < 4) {
#pragma unroll
        for (int p = 0; p < 16; ++p) red[s][p][oc] = acc[p];
    }
    __syncthreads();

    for (int e = tid; e < 432; e += 128) {
        int pp = e / 27, o = e % 27;
        om_s[pp][o] = red[0][pp][o] + red[1][pp][o] + red[2][pp][o]
                    + red[3][pp][o] + omb[o];
    }
    __syncthreads();

    for (int e = tid; e < 144; e += 128) {
        int pp = e / 9, k = e % 9;
        float dy = om_s[pp][2 * k];
        float dx = om_s[pp][2 * k + 1];
        float m  = 2.f / (1.f + expf(-om_s[pp][18 + k]));
        int ky = k / 3, kx = k % 3;
        int wo = wch * 16 + pp;
        float py = (float)(ho - 1 + ky) + dy;
        float px = (float)(wo - 1 + kx) + dx;
        int pix = b * NPIX + ho * WW + wo;
        g_offmask[pix * 9 + k] = make_float4(py, px, m, 0.f);
    }
}

// ---------------------------------------------------------------------------
// Kernel 2: fused bilinear sampling + HMMA tf32 GEMM.
// 288 CTAs x 512 threads. CTA tile 128 px x 256 F, warp tile 32x64.
// A smem in fragment order with XOR swizzle; B pre-shuffled (linear copy).
// ---------------------------------------------------------------------------
__global__ void __launch_bounds__(512, 1) dcn_mma_kernel(
    const float* __restrict__ x, const float* __restrict__ bias,
    float* __restrict__ out)
{
    extern __shared__ float smem[];
    float* AsArr[2] = { smem,            smem + 4096  };
    float* BsArr[2] = { smem + 8192,     smem + 16384 };

    int tid  = threadIdx.x;
    int wid  = tid >> 5;
    int lane = tid & 31;

    int tile0 = blockIdx.x * 128;
    int b = tile0 / NPIX;
    const float* xb = x + (size_t)b * NPIX * CC;

    // sampler identity: one pixel, one 8-channel ktile per thread
    int spx  = tid >> 2;          // 0..127
    int sub  = tid & 3;           // ktile within 32-chunk
    int r    = spx & 15;
    int smt  = spx >> 4;
    uint32_t fragbase = (uint32_t)((smt * 4 + sub) << 7);
    uint32_t perm = (uint32_t)(((sub << 1) | (smt & 1)) & 7);
    int pix = tile0 + spx;

    // gemm identity
    int wm = wid & 3;             // M warp (32 rows)
    int wn = wid >> 2;            // N warp (64 cols)

    float acc[2][8][4];
#pragma unroll
    for (int i = 0; i < 2; ++i)
#pragma unroll
        for (int j = 0; j < 8; ++j)
#pragma unroll
            for (int q = 0; q < 4; ++q) acc[i][j][q] = 0.f;

    // persistent per-tap sampling state
    float w00 = 0.f, w01 = 0.f, w10 = 0.f, w11 = 0.f;
    uint32_t o00 = 0, o01 = 0, o10 = 0, o11 = 0;   // float offsets into xb

    auto fill = [&](int c) {
        int tap = c >> 3, cb = c & 7;
        if (cb == 0) {
            float4 om = g_offmask[pix * 9 + tap];
            float fy0 = floorf(om.x), fx0 = floorf(om.y);
            int iy0 = (int)fy0, ix0 = (int)fx0;
            float fy = om.x - fy0, fx = om.y - fx0;
            float m = om.z;
            w00 = (1.f - fy) * (1.f - fx) * m;
            w01 = (1.f - fy) * fx * m;
            w10 = fy * (1.f - fx) * m;
            w11 = fy * fx * m;
            if (iy0 < 0  || iy0 >= HH)     { w00 = 0.f; w01 = 0.f; }
            if (iy0 < -1 || iy0 >= HH - 1) { w10 = 0.f; w11 = 0.f; }
            if (ix0 < 0  || ix0 >= WW)     { w00 = 0.f; w10 = 0.f; }
            if (ix0 < -1 || ix0 >= WW - 1) { w01 = 0.f; w11 = 0.f; }
            int y0c = min(max(iy0, 0), HH - 1);
            int y1c = min(max(iy0 + 1, 0), HH - 1);
            int x0c = min(max(ix0, 0), WW - 1);
            int x1c = min(max(ix0 + 1, 0), WW - 1);
            o00 = (uint32_t)((y0c * WW + x0c) * CC);
            o01 = (uint32_t)((y0c * WW + x1c) * CC);
            o10 = (uint32_t)((y1c * WW + x0c) * CC);
            o11 = (uint32_t)((y1c * WW + x1c) * CC);
        }
        int s = c & 1;
        // ---- A: sample 8 channels of ktile `sub` for pixel spx ----
        {
            int cbase = cb * 32 + sub * 8;
            float va[8];
#pragma unroll
            for (int g = 0; g < 2; ++g) {
                int cg = cbase + g * 4;
                float4 v00 = *(const float4*)(xb + o00 + cg);
                float4 v01 = *(const float4*)(xb + o01 + cg);
                float4 v10 = *(const float4*)(xb + o10 + cg);
                float4 v11 = *(const float4*)(xb + o11 + cg);
                va[g*4+0] = w00*v00.x + w01*v01.x + w10*v10.x + w11*v11.x;
                va[g*4+1] = w00*v00.y + w01*v01.y + w10*v10.y + w11*v11.y;
                va[g*4+2] = w00*v00.z + w01*v01.z + w10*v10.z + w11*v11.z;
                va[g*4+3] = w00*v00.w + w01*v01.w + w10*v10.w + w11*v11.w;
            }
            float* As = AsArr[s];
#pragma unroll
            for (int cc2 = 0; cc2 < 8; ++cc2) {
                uint32_t t  = (uint32_t)((r & 7) * 4 + (cc2 & 3));
                uint32_t rg = (uint32_t)((r >> 3) + 2 * (cc2 >> 2));
                uint32_t w  = 4u * t + rg;
                uint32_t pw = w ^ ((((w >> 5) ^ perm) & 7u) << 2);
                As[fragbase + pw] = tf32r(va[cc2]);
            }
        }
        // ---- B: linear copy of pre-shuffled chunk (8192 floats) ----
        {
            const float4* src = (const float4*)g_kernB + (size_t)c * 2048;
            float4* dst = (float4*)BsArr[s];
#pragma unroll
            for (int i = 0; i < 4; ++i)
                dst[tid + i * 512] = src[tid + i * 512];
        }
    };

    auto domma = [&](int c) {
        int s = c & 1;
        const float* As = AsArr[s];
        const float* Bs = BsArr[s];
#pragma unroll
        for (int ktp = 0; ktp < 2; ++ktp) {
            uint4 bf[8];
#pragma unroll
            for (int nt = 0; nt < 8; ++nt) {
                int ntg = wn * 8 + nt;
                bf[nt] = *(const uint4*)(Bs + (size_t)((ktp * 32 + ntg) * 32 + lane) * 4);
            }
#pragma unroll
            for (int kh = 0; kh < 2; ++kh) {
                int kt = ktp * 2 + kh;
                uint4 af[2];
#pragma unroll
                for (int mt = 0; mt < 2; ++mt) {
                    int amt = wm * 2 + mt;
                    uint32_t pm = (uint32_t)(((kt << 1) | (amt & 1)) & 7);
                    uint32_t w = (uint32_t)(lane * 4);
                    uint32_t pw = w ^ ((((w >> 5) ^ pm) & 7u) << 2);
                    af[mt] = *(const uint4*)(As + ((uint32_t)((amt * 4 + kt) << 7) + pw));
                }
#pragma unroll
                for (int mt = 0; mt < 2; ++mt)
#pragma unroll
                    for (int nt = 0; nt < 8; ++nt) {
                        uint32_t b0 = kh ? bf[nt].z : bf[nt].x;
                        uint32_t b1 = kh ? bf[nt].w : bf[nt].y;
                        mma_tf32(acc[mt][nt], af[mt].x, af[mt].y, af[mt].z, af[mt].w, b0, b1);
                    }
            }
        }
    };

    fill(0);
    __syncthreads();
    for (int it = 0; it < NCHUNK; ++it) {
        if (it + 1 < NCHUNK) fill(it + 1);
        domma(it);
        __syncthreads();
    }

    // ---- epilogue: acc -> global with bias ----
    {
        int col0 = wn * 64;
        int qrow = lane >> 2;
        int qcol = (lane & 3) * 2;
        float2 bv[8];
#pragma unroll
        for (int nt = 0; nt < 8; ++nt)
            bv[nt] = *(const float2*)(bias + col0 + nt * 8 + qcol);
#pragma unroll
        for (int mt = 0; mt < 2; ++mt) {
            int row = tile0 + wm * 32 + mt * 16 + qrow;
#pragma unroll
            for (int nt = 0; nt < 8; ++nt) {
                int col = col0 + nt * 8 + qcol;
                float2 lo, hi;
                lo.x = acc[mt][nt][0] + bv[nt].x;
                lo.y = acc[mt][nt][1] + bv[nt].y;
                hi.x = acc[mt][nt][2] + bv[nt].x;
                hi.y = acc[mt][nt][3] + bv[nt].y;
                *(float2*)(out + (size_t)row * FF + col)       = lo;
                *(float2*)(out + (size_t)(row + 8) * FF + col) = hi;
            }
        }
    }
}

#define SMEM_BYTES (24576 * 4)   // 96 KB

extern "C" void kernel_launch(void* const* d_in, const int* in_sizes, int n_in,
                              void* d_out, int out_size)
{
    const float* x    = (const float*)d_in[0];  // [4,96,96,256]
    const float* omk  = (const float*)d_in[1];  // [3,3,256,27]
    const float* omb  = (const float*)d_in[2];  // [27]
    const float* kern = (const float*)d_in[3];  // [2304,256]
    const float* bias = (const float*)d_in[4];  // [256]
    float* out = (float*)d_out;                 // [36864,256]

    cudaFuncSetAttribute(dcn_mma_kernel,
                         cudaFuncAttributeMaxDynamicSharedMemorySize, SMEM_BYTES);

    transpose_kernel<<<576, 256>>>(kern);
    om_conv_kernel<<<BB * 96 * 6, 128>>>(x, omk, omb);
    dcn_mma_kernel<<<TOTPIX / 128, 512, SMEM_BYTES>>>(x, bias, out);
}

// round 4
// speedup vs baseline: 2.7690x; 1.5782x over previous
#include <cuda_runtime.h>
#include <math.h>
#include <stdint.h>

#define HH 96
#define WW 96
#define CC 256
#define FF 256
#define BB 4
#define NPIX (HH*WW)        // 9216
#define TOTPIX (BB*NPIX)    // 36864
#define NCHUNK 72           // 2304 / 32

// scratch: per (pixel, tap): (py, px, mask, 0)
__device__ float4 g_offmask[TOTPIX * 9];
// main weights in mma-fragment order: [chunk72][ktp2][ntile32][lane32][4]
__device__ float g_kernB[NCHUNK * 2 * 32 * 32 * 4];
// om weights in mma-fragment order: [chunk72][ktp2][ntile4][lane32][4] (n>=27 zero)
__device__ float g_omkB[NCHUNK * 2 * 4 * 32 * 4];

__device__ __forceinline__ float tf32r(float f) {
    float r;
    asm("cvt.rna.tf32.f32 %0, %1;" : "=f"(r) : "f"(f));
    return r;
}
__device__ __forceinline__ uint32_t smem_u32(const void* p) {
    uint32_t a;
    asm("{ .reg .u64 t; cvta.to.shared.u64 t, %1; cvt.u32.u64 %0, t; }" : "=r"(a) : "l"(p));
    return a;
}

#define CP_ASYNC16(dst, src) \
    asm volatile("cp.async.cg.shared.global [%0], [%1], 16;" :: "r"(dst), "l"(src) : "memory")
#define CP_COMMIT() asm volatile("cp.async.commit_group;" ::: "memory")
#define CP_WAIT0()  asm volatile("cp.async.wait_group 0;" ::: "memory")

__device__ __forceinline__ void mma_tf32(
    float* d, uint32_t a0, uint32_t a1, uint32_t a2, uint32_t a3,
    uint32_t b0, uint32_t b1)
{
    asm volatile(
        "mma.sync.aligned.m16n8k8.row.col.f32.tf32.tf32.f32 "
        "{%0,%1,%2,%3}, {%4,%5,%6,%7}, {%8,%9}, {%0,%1,%2,%3};"
        : "+f"(d[0]), "+f"(d[1]), "+f"(d[2]), "+f"(d[3])
        : "r"(a0), "r"(a1), "r"(a2), "r"(a3), "r"(b0), "r"(b1));
}

// ---------------------------------------------------------------------------
// Kernel 0a: main weight shuffle into fragment order (tf32-rounded).
// ---------------------------------------------------------------------------
__global__ void __launch_bounds__(256) transpose_kernel(const float* __restrict__ kern)
{
    int idx = blockIdx.x * 256 + threadIdx.x;    // 0 .. 147455
    int t   = idx & 31;
    int nt  = (idx >> 5) & 31;
    int ktp = (idx >> 10) & 1;
    int ch  = idx >> 11;
    int n = nt * 8 + (t >> 2);
    int kbase = ch * 32 + ktp * 16 + (t & 3);
    float4 v;
    v.x = tf32r(kern[(kbase + 0)  * 256 + n]);
    v.y = tf32r(kern[(kbase + 4)  * 256 + n]);
    v.z = tf32r(kern[(kbase + 8)  * 256 + n]);
    v.w = tf32r(kern[(kbase + 12) * 256 + n]);
    ((float4*)g_kernB)[idx] = v;
}

// ---------------------------------------------------------------------------
// Kernel 0b: om weight shuffle. omk flat: [(tap*256+c)*27 + n], N padded to 32.
// ---------------------------------------------------------------------------
__global__ void __launch_bounds__(256) om_transpose_kernel(const float* __restrict__ omk)
{
    int idx = blockIdx.x * 256 + threadIdx.x;    // 0 .. 18431
    int t   = idx & 31;
    int nt  = (idx >> 5) & 3;
    int ktp = (idx >> 7) & 1;
    int ch  = idx >> 8;
    int n = nt * 8 + (t >> 2);
    int kbase = ch * 32 + ktp * 16 + (t & 3);
    float4 v = make_float4(0.f, 0.f, 0.f, 0.f);
    if (n < 27) {
        v.x = tf32r(omk[(kbase + 0)  * 27 + n]);
        v.y = tf32r(omk[(kbase + 4)  * 27 + n]);
        v.z = tf32r(omk[(kbase + 8)  * 27 + n]);
        v.w = tf32r(omk[(kbase + 12) * 27 + n]);
    }
    ((float4*)g_omkB)[idx] = v;
}

// ---------------------------------------------------------------------------
// Kernel 1: om conv as HMMA tf32 GEMM. 288 CTAs x 128 threads.
// Tile 128 px x 32 (27 used). A chunk [128 x 32] from integer-tap rows.
// ---------------------------------------------------------------------------
#define OM_SMEM ((8192 + 2048 + 128*28) * 4)

__global__ void __launch_bounds__(128) om_mma_kernel(
    const float* __restrict__ x, const float* __restrict__ omb)
{
    extern __shared__ float sm[];
    float* AsArr[2] = { sm,        sm + 4096 };
    float* BsArr[2] = { sm + 8192, sm + 9216 };
    float* om_s     = sm + 10240;             // [128][28]
    uint32_t sbB = smem_u32(sm + 8192);

    int tid  = threadIdx.x;
    int wid  = tid >> 5;
    int lane = tid & 31;

    int tile0 = blockIdx.x * 128;
    int b = tile0 / NPIX;
    const float* xb = x + (size_t)b * NPIX * CC;

    int px = tid;
    int pp = tile0 + px;
    int ho = (pp % NPIX) / WW;
    int wo = pp % WW;

    int r   = px & 15;
    int smt = px >> 4;

    float acc[2][4][4];
#pragma unroll
    for (int i = 0; i < 2; ++i)
#pragma unroll
        for (int j = 0; j < 4; ++j)
#pragma unroll
            for (int q = 0; q < 4; ++q) acc[i][j][q] = 0.f;

    const float* rowp = xb;
    bool valid = false;

    auto fill = [&](int c) {
        int tap = c >> 3, cb = c & 7;
        int s = c & 1;
        if (cb == 0) {
            int ky = tap / 3, kx = tap % 3;
            int y  = ho - 1 + ky;
            int xx = wo - 1 + kx;
            valid = (y >= 0 && y < HH && xx >= 0 && xx < WW);
            rowp = xb + (size_t)(y * WW + xx) * CC;
        }
        // B chunk via cp.async: 1024 floats = 256 float4, 2 per thread
        {
            const float4* src = (const float4*)g_omkB + (size_t)c * 256;
            uint32_t bdst = sbB + (uint32_t)(s ? 4096 : 0);
#pragma unroll
            for (int i = 0; i < 2; ++i)
                CP_ASYNC16(bdst + (uint32_t)(tid + i * 128) * 16,
                           (const void*)(src + tid + i * 128));
            CP_COMMIT();
        }
        // A: 32 channels of this pixel's tap row
        float* As = AsArr[s];
#pragma unroll
        for (int sub = 0; sub < 4; ++sub) {
            float va[8];
#pragma unroll
            for (int g = 0; g < 2; ++g) {
                float4 v = make_float4(0.f, 0.f, 0.f, 0.f);
                if (valid) v = *(const float4*)(rowp + cb * 32 + sub * 8 + g * 4);
                va[g*4+0] = v.x; va[g*4+1] = v.y; va[g*4+2] = v.z; va[g*4+3] = v.w;
            }
            uint32_t fragbase = (uint32_t)((smt * 4 + sub) << 7);
            uint32_t perm = (uint32_t)(((sub << 1) | (smt & 1)) & 7);
#pragma unroll
            for (int cc2 = 0; cc2 < 8; ++cc2) {
                uint32_t t  = (uint32_t)((r & 7) * 4 + (cc2 & 3));
                uint32_t rg = (uint32_t)((r >> 3) + 2 * (cc2 >> 2));
                uint32_t w  = 4u * t + rg;
                uint32_t pw = w ^ ((((w >> 5) ^ perm) & 7u) << 2);
                As[fragbase + pw] = tf32r(va[cc2]);
            }
        }
    };

    auto domma = [&](int c) {
        int s = c & 1;
        const float* As = AsArr[s];
        const float* Bs = BsArr[s];
#pragma unroll
        for (int ktp = 0; ktp < 2; ++ktp) {
            uint4 bf[4];
#pragma unroll
            for (int nt = 0; nt < 4; ++nt)
                bf[nt] = *(const uint4*)(Bs + (size_t)((ktp * 4 + nt) * 32 + lane) * 4);
#pragma unroll
            for (int kh = 0; kh < 2; ++kh) {
                int kt = ktp * 2 + kh;
                uint4 af[2];
#pragma unroll
                for (int mt = 0; mt < 2; ++mt) {
                    int amt = wid * 2 + mt;
                    uint32_t pm = (uint32_t)(((kt << 1) | (amt & 1)) & 7);
                    uint32_t w = (uint32_t)(lane * 4);
                    uint32_t pw = w ^ ((((w >> 5) ^ pm) & 7u) << 2);
                    af[mt] = *(const uint4*)(As + ((uint32_t)((amt * 4 + kt) << 7) + pw));
                }
#pragma unroll
                for (int mt = 0; mt < 2; ++mt)
#pragma unroll
                    for (int nt = 0; nt < 4; ++nt) {
                        uint32_t b0 = kh ? bf[nt].z : bf[nt].x;
                        uint32_t b1 = kh ? bf[nt].w : bf[nt].y;
                        mma_tf32(acc[mt][nt], af[mt].x, af[mt].y, af[mt].z, af[mt].w, b0, b1);
                    }
            }
        }
    };

    fill(0);
    CP_WAIT0();
    __syncthreads();
    for (int it = 0; it < NCHUNK; ++it) {
        if (it + 1 < NCHUNK) fill(it + 1);
        domma(it);
        CP_WAIT0();
        __syncthreads();
    }

    // ---- epilogue: acc (+bias) -> om_s ----
    {
        int qrow = lane >> 2;
        int qcol = (lane & 3) * 2;
#pragma unroll
        for (int mt = 0; mt < 2; ++mt) {
            int row = wid * 32 + mt * 16 + qrow;
#pragma unroll
            for (int nt = 0; nt < 4; ++nt) {
                int col = nt * 8 + qcol;
                if (col < 27) {
                    float ob = omb[col];
                    om_s[row * 28 + col]       = acc[mt][nt][0] + ob;
                    om_s[(row + 8) * 28 + col] = acc[mt][nt][2] + ob;
                }
                if (col + 1 < 27) {
                    float ob = omb[col + 1];
                    om_s[row * 28 + col + 1]       = acc[mt][nt][1] + ob;
                    om_s[(row + 8) * 28 + col + 1] = acc[mt][nt][3] + ob;
                }
            }
        }
    }
    __syncthreads();

    // ---- offsets/mask -> g_offmask ----
#pragma unroll
    for (int k = 0; k < 9; ++k) {
        float dy = om_s[px * 28 + 2 * k];
        float dx = om_s[px * 28 + 2 * k + 1];
        float m  = 2.f / (1.f + expf(-om_s[px * 28 + 18 + k]));
        int ky = k / 3, kx = k % 3;
        float py = (float)(ho - 1 + ky) + dy;
        float pxx = (float)(wo - 1 + kx) + dx;
        g_offmask[pp * 9 + k] = make_float4(py, pxx, m, 0.f);
    }
}

// ---------------------------------------------------------------------------
// Kernel 2: fused bilinear sampling + HMMA tf32 GEMM (B via cp.async).
// 288 CTAs x 512 threads. CTA tile 128 px x 256 F, warp tile 32x64.
// ---------------------------------------------------------------------------
__global__ void __launch_bounds__(512, 1) dcn_mma_kernel(
    const float* __restrict__ x, const float* __restrict__ bias,
    float* __restrict__ out)
{
    extern __shared__ float smem[];
    float* AsArr[2] = { smem,        smem + 4096  };
    float* BsArr[2] = { smem + 8192, smem + 16384 };
    uint32_t sbB = smem_u32(smem + 8192);

    int tid  = threadIdx.x;
    int wid  = tid >> 5;
    int lane = tid & 31;

    int tile0 = blockIdx.x * 128;
    int b = tile0 / NPIX;
    const float* xb = x + (size_t)b * NPIX * CC;

    int spx  = tid >> 2;
    int sub  = tid & 3;
    int r    = spx & 15;
    int smt  = spx >> 4;
    uint32_t fragbase = (uint32_t)((smt * 4 + sub) << 7);
    uint32_t perm = (uint32_t)(((sub << 1) | (smt & 1)) & 7);
    int pix = tile0 + spx;

    int wm = wid & 3;
    int wn = wid >> 2;

    float acc[2][8][4];
#pragma unroll
    for (int i = 0; i < 2; ++i)
#pragma unroll
        for (int j = 0; j < 8; ++j)
#pragma unroll
            for (int q = 0; q < 4; ++q) acc[i][j][q] = 0.f;

    float w00 = 0.f, w01 = 0.f, w10 = 0.f, w11 = 0.f;
    uint32_t o00 = 0, o01 = 0, o10 = 0, o11 = 0;

    auto fill = [&](int c) {
        int tap = c >> 3, cb = c & 7;
        int s = c & 1;
        if (cb == 0) {
            float4 om = g_offmask[pix * 9 + tap];
            float fy0 = floorf(om.x), fx0 = floorf(om.y);
            int iy0 = (int)fy0, ix0 = (int)fx0;
            float fy = om.x - fy0, fx = om.y - fx0;
            float m = om.z;
            w00 = (1.f - fy) * (1.f - fx) * m;
            w01 = (1.f - fy) * fx * m;
            w10 = fy * (1.f - fx) * m;
            w11 = fy * fx * m;
            if (iy0 < 0  || iy0 >= HH)     { w00 = 0.f; w01 = 0.f; }
            if (iy0 < -1 || iy0 >= HH - 1) { w10 = 0.f; w11 = 0.f; }
            if (ix0 < 0  || ix0 >= WW)     { w00 = 0.f; w10 = 0.f; }
            if (ix0 < -1 || ix0 >= WW - 1) { w01 = 0.f; w11 = 0.f; }
            int y0c = min(max(iy0, 0), HH - 1);
            int y1c = min(max(iy0 + 1, 0), HH - 1);
            int x0c = min(max(ix0, 0), WW - 1);
            int x1c = min(max(ix0 + 1, 0), WW - 1);
            o00 = (uint32_t)((y0c * WW + x0c) * CC);
            o01 = (uint32_t)((y0c * WW + x1c) * CC);
            o10 = (uint32_t)((y1c * WW + x0c) * CC);
            o11 = (uint32_t)((y1c * WW + x1c) * CC);
        }
        // B chunk via cp.async: 2048 float4, 4 per thread
        {
            const float4* src = (const float4*)g_kernB + (size_t)c * 2048;
            uint32_t bdst = sbB + (uint32_t)(s ? 32768 : 0);
#pragma unroll
            for (int i = 0; i < 4; ++i)
                CP_ASYNC16(bdst + (uint32_t)(tid + i * 512) * 16,
                           (const void*)(src + tid + i * 512));
            CP_COMMIT();
        }
        // A: sample 8 channels of ktile `sub` for pixel spx
        {
            int cbase = cb * 32 + sub * 8;
            float va[8];
#pragma unroll
            for (int g = 0; g < 2; ++g) {
                int cg = cbase + g * 4;
                float4 v00 = *(const float4*)(xb + o00 + cg);
                float4 v01 = *(const float4*)(xb + o01 + cg);
                float4 v10 = *(const float4*)(xb + o10 + cg);
                float4 v11 = *(const float4*)(xb + o11 + cg);
                va[g*4+0] = w00*v00.x + w01*v01.x + w10*v10.x + w11*v11.x;
                va[g*4+1] = w00*v00.y + w01*v01.y + w10*v10.y + w11*v11.y;
                va[g*4+2] = w00*v00.z + w01*v01.z + w10*v10.z + w11*v11.z;
                va[g*4+3] = w00*v00.w + w01*v01.w + w10*v10.w + w11*v11.w;
            }
            float* As = AsArr[s];
#pragma unroll
            for (int cc2 = 0; cc2 < 8; ++cc2) {
                uint32_t t  = (uint32_t)((r & 7) * 4 + (cc2 & 3));
                uint32_t rg = (uint32_t)((r >> 3) + 2 * (cc2 >> 2));
                uint32_t w  = 4u * t + rg;
                uint32_t pw = w ^ ((((w >> 5) ^ perm) & 7u) << 2);
                As[fragbase + pw] = tf32r(va[cc2]);
            }
        }
    };

    auto domma = [&](int c) {
        int s = c & 1;
        const float* As = AsArr[s];
        const float* Bs = BsArr[s];
#pragma unroll
        for (int ktp = 0; ktp < 2; ++ktp) {
            uint4 bf[8];
#pragma unroll
            for (int nt = 0; nt < 8; ++nt) {
                int ntg = wn * 8 + nt;
                bf[nt] = *(const uint4*)(Bs + (size_t)((ktp * 32 + ntg) * 32 + lane) * 4);
            }
#pragma unroll
            for (int kh = 0; kh < 2; ++kh) {
                int kt = ktp * 2 + kh;
                uint4 af[2];
#pragma unroll
                for (int mt = 0; mt < 2; ++mt) {
                    int amt = wm * 2 + mt;
                    uint32_t pm = (uint32_t)(((kt << 1) | (amt & 1)) & 7);
                    uint32_t w = (uint32_t)(lane * 4);
                    uint32_t pw = w ^ ((((w >> 5) ^ pm) & 7u) << 2);
                    af[mt] = *(const uint4*)(As + ((uint32_t)((amt * 4 + kt) << 7) + pw));
                }
#pragma unroll
                for (int mt = 0; mt < 2; ++mt)
#pragma unroll
                    for (int nt = 0; nt < 8; ++nt) {
                        uint32_t b0 = kh ? bf[nt].z : bf[nt].x;
                        uint32_t b1 = kh ? bf[nt].w : bf[nt].y;
                        mma_tf32(acc[mt][nt], af[mt].x, af[mt].y, af[mt].z, af[mt].w, b0, b1);
                    }
            }
        }
    };

    fill(0);
    CP_WAIT0();
    __syncthreads();
    for (int it = 0; it < NCHUNK; ++it) {
        if (it + 1 < NCHUNK) fill(it + 1);
        domma(it);
        CP_WAIT0();
        __syncthreads();
    }

    // ---- epilogue: acc -> global with bias ----
    {
        int col0 = wn * 64;
        int qrow = lane >> 2;
        int qcol = (lane & 3) * 2;
        float2 bv[8];
#pragma unroll
        for (int nt = 0; nt < 8; ++nt)
            bv[nt] = *(const float2*)(bias + col0 + nt * 8 + qcol);
#pragma unroll
        for (int mt = 0; mt < 2; ++mt) {
            int row = tile0 + wm * 32 + mt * 16 + qrow;
#pragma unroll
            for (int nt = 0; nt < 8; ++nt) {
                int col = col0 + nt * 8 + qcol;
                float2 lo, hi;
                lo.x = acc[mt][nt][0] + bv[nt].x;
                lo.y = acc[mt][nt][1] + bv[nt].y;
                hi.x = acc[mt][nt][2] + bv[nt].x;
                hi.y = acc[mt][nt][3] + bv[nt].y;
                *(float2*)(out + (size_t)row * FF + col)       = lo;
                *(float2*)(out + (size_t)(row + 8) * FF + col) = hi;
            }
        }
    }
}

#define SMEM_BYTES (24576 * 4)   // 96 KB

extern "C" void kernel_launch(void* const* d_in, const int* in_sizes, int n_in,
                              void* d_out, int out_size)
{
    const float* x    = (const float*)d_in[0];  // [4,96,96,256]
    const float* omk  = (const float*)d_in[1];  // [3,3,256,27]
    const float* omb  = (const float*)d_in[2];  // [27]
    const float* kern = (const float*)d_in[3];  // [2304,256]
    const float* bias = (const float*)d_in[4];  // [256]
    float* out = (float*)d_out;                 // [36864,256]

    cudaFuncSetAttribute(dcn_mma_kernel,
                         cudaFuncAttributeMaxDynamicSharedMemorySize, SMEM_BYTES);
    cudaFuncSetAttribute(om_mma_kernel,
                         cudaFuncAttributeMaxDynamicSharedMemorySize, OM_SMEM);

    transpose_kernel<<<576, 256>>>(kern);
    om_transpose_kernel<<<72, 256>>>(omk);
    om_mma_kernel<<<TOTPIX / 128, 128, OM_SMEM>>>(x, omb);
    dcn_mma_kernel<<<TOTPIX / 128, 512, SMEM_BYTES>>>(x, bias, out);
}

// round 5
// speedup vs baseline: 2.9429x; 1.0628x over previous
#include <cuda_runtime.h>
#include <math.h>
#include <stdint.h>

#define HH 96
#define WW 96
#define CC 256
#define FF 256
#define BB 4
#define NPIX (HH*WW)        // 9216
#define TOTPIX (BB*NPIX)    // 36864
#define NCHUNK 72           // 2304 / 32

// scratch: per (pixel, tap): (py, px, mask, 0)
__device__ float4 g_offmask[TOTPIX * 9];
// main weights in mma-fragment order: [chunk72][ktp2][ntile32][lane32][4]
__device__ float g_kernB[NCHUNK * 2 * 32 * 32 * 4];
// om weights in mma-fragment order: [chunk72][ktp2][ntile4][lane32][4] (n>=27 zero)
__device__ float g_omkB[NCHUNK * 2 * 4 * 32 * 4];

__device__ __forceinline__ float tf32r(float f) {
    float r;
    asm("cvt.rna.tf32.f32 %0, %1;" : "=f"(r) : "f"(f));
    return r;
}
__device__ __forceinline__ uint32_t smem_u32(const void* p) {
    uint32_t a;
    asm("{ .reg .u64 t; cvta.to.shared.u64 t, %1; cvt.u32.u64 %0, t; }" : "=r"(a) : "l"(p));
    return a;
}

#define CP_ASYNC16(dst, src) \
    asm volatile("cp.async.cg.shared.global [%0], [%1], 16;" :: "r"(dst), "l"(src) : "memory")
#define CP_COMMIT() asm volatile("cp.async.commit_group;" ::: "memory")
#define CP_WAIT0()  asm volatile("cp.async.wait_group 0;" ::: "memory")

__device__ __forceinline__ void mma_tf32(
    float* d, uint32_t a0, uint32_t a1, uint32_t a2, uint32_t a3,
    uint32_t b0, uint32_t b1)
{
    asm volatile(
        "mma.sync.aligned.m16n8k8.row.col.f32.tf32.tf32.f32 "
        "{%0,%1,%2,%3}, {%4,%5,%6,%7}, {%8,%9}, {%0,%1,%2,%3};"
        : "+f"(d[0]), "+f"(d[1]), "+f"(d[2]), "+f"(d[3])
        : "r"(a0), "r"(a1), "r"(a2), "r"(a3), "r"(b0), "r"(b1));
}

// ---------------------------------------------------------------------------
// Kernel 0a: main weight shuffle into fragment order (tf32-rounded).
// ---------------------------------------------------------------------------
__global__ void __launch_bounds__(256) transpose_kernel(const float* __restrict__ kern)
{
    int idx = blockIdx.x * 256 + threadIdx.x;    // 0 .. 147455
    int t   = idx & 31;
    int nt  = (idx >> 5) & 31;
    int ktp = (idx >> 10) & 1;
    int ch  = idx >> 11;
    int n = nt * 8 + (t >> 2);
    int kbase = ch * 32 + ktp * 16 + (t & 3);
    float4 v;
    v.x = tf32r(kern[(kbase + 0)  * 256 + n]);
    v.y = tf32r(kern[(kbase + 4)  * 256 + n]);
    v.z = tf32r(kern[(kbase + 8)  * 256 + n]);
    v.w = tf32r(kern[(kbase + 12) * 256 + n]);
    ((float4*)g_kernB)[idx] = v;
}

// ---------------------------------------------------------------------------
// Kernel 0b: om weight shuffle. omk flat: [(tap*256+c)*27 + n], N padded to 32.
// ---------------------------------------------------------------------------
__global__ void __launch_bounds__(256) om_transpose_kernel(const float* __restrict__ omk)
{
    int idx = blockIdx.x * 256 + threadIdx.x;    // 0 .. 18431
    int t   = idx & 31;
    int nt  = (idx >> 5) & 3;
    int ktp = (idx >> 7) & 1;
    int ch  = idx >> 8;
    int n = nt * 8 + (t >> 2);
    int kbase = ch * 32 + ktp * 16 + (t & 3);
    float4 v = make_float4(0.f, 0.f, 0.f, 0.f);
    if (n < 27) {
        v.x = tf32r(omk[(kbase + 0)  * 27 + n]);
        v.y = tf32r(omk[(kbase + 4)  * 27 + n]);
        v.z = tf32r(omk[(kbase + 8)  * 27 + n]);
        v.w = tf32r(omk[(kbase + 12) * 27 + n]);
    }
    ((float4*)g_omkB)[idx] = v;
}

// ---------------------------------------------------------------------------
// Kernel 1: om conv as HMMA tf32 GEMM. 576 CTAs x 128 threads.
// Tile 64 px x 32 (27 used). Load-ahead pipeline; 2 slots per thread.
// ---------------------------------------------------------------------------
__global__ void __launch_bounds__(128) om_mma_kernel(
    const float* __restrict__ x, const float* __restrict__ omb)
{
    __shared__ float smA[2][2048];
    __shared__ float smB[2][1024];
    __shared__ float om_s[64 * 28];
    uint32_t sbB = smem_u32(&smB[0][0]);

    int tid  = threadIdx.x;
    int wid  = tid >> 5;
    int lane = tid & 31;

    int tile0 = blockIdx.x * 64;
    int b = tile0 / NPIX;
    const float* xb = x + (size_t)b * NPIX * CC;

    // two (px, sub) slots per thread
    int sub  = tid & 3;
    int px0  = tid >> 2;          // 0..31
    int px1  = px0 + 32;
    int pp0  = tile0 + px0;
    int pp1  = tile0 + px1;
    int ho0  = (pp0 % NPIX) / WW, wo0 = pp0 % WW;
    int ho1  = (pp1 % NPIX) / WW, wo1 = pp1 % WW;

    // A store addresses (invariant)
    uint32_t ast0[8], ast1[8];
    {
        int r0 = px0 & 15, smt0 = px0 >> 4;
        int r1 = px1 & 15, smt1 = px1 >> 4;
        uint32_t fb0 = (uint32_t)((smt0 * 4 + sub) << 7);
        uint32_t fb1 = (uint32_t)((smt1 * 4 + sub) << 7);
        uint32_t pm0 = (uint32_t)(((sub << 1) | (smt0 & 1)) & 7);
        uint32_t pm1 = (uint32_t)(((sub << 1) | (smt1 & 1)) & 7);
#pragma unroll
        for (int cc2 = 0; cc2 < 8; ++cc2) {
            uint32_t t0  = (uint32_t)((r0 & 7) * 4 + (cc2 & 3));
            uint32_t rg0 = (uint32_t)((r0 >> 3) + 2 * (cc2 >> 2));
            uint32_t w0  = 4u * t0 + rg0;
            ast0[cc2] = fb0 + (w0 ^ ((((w0 >> 5) ^ pm0) & 7u) << 2));
            uint32_t t1  = (uint32_t)((r1 & 7) * 4 + (cc2 & 3));
            uint32_t rg1 = (uint32_t)((r1 >> 3) + 2 * (cc2 >> 2));
            uint32_t w1  = 4u * t1 + rg1;
            ast1[cc2] = fb1 + (w1 ^ ((((w1 >> 5) ^ pm1) & 7u) << 2));
        }
    }

    float acc[4][4];
#pragma unroll
    for (int j = 0; j < 4; ++j)
#pragma unroll
        for (int q = 0; q < 4; ++q) acc[j][q] = 0.f;

    const float* rowp0 = xb; bool valid0 = false;
    const float* rowp1 = xb; bool valid1 = false;

    auto tapsetup = [&](int tap) {
        int ky = tap / 3, kx = tap % 3;
        int y0 = ho0 - 1 + ky, x0 = wo0 - 1 + kx;
        valid0 = (y0 >= 0 && y0 < HH && x0 >= 0 && x0 < WW);
        rowp0 = xb + (size_t)(y0 * WW + x0) * CC;
        int y1 = ho1 - 1 + ky, x1 = wo1 - 1 + kx;
        valid1 = (y1 >= 0 && y1 < HH && x1 >= 0 && x1 < WW);
        rowp1 = xb + (size_t)(y1 * WW + x1) * CC;
    };

    auto cpasyncB = [&](int c, int s) {
        const float4* src = (const float4*)g_omkB + (size_t)c * 256;
        uint32_t bdst = sbB + (uint32_t)s * 4096;
#pragma unroll
        for (int i = 0; i < 2; ++i)
            CP_ASYNC16(bdst + (uint32_t)(tid + i * 128) * 16,
                       (const void*)(src + tid + i * 128));
        CP_COMMIT();
    };

    auto domma = [&](int s) {
        const float* As = smA[s];
        const float* Bs = smB[s];
#pragma unroll
        for (int ktp = 0; ktp < 2; ++ktp) {
            uint4 af[2];
#pragma unroll
            for (int kh = 0; kh < 2; ++kh) {
                int kt = ktp * 2 + kh;
                uint32_t pm = (uint32_t)(((kt << 1) | (wid & 1)) & 7);
                uint32_t w = (uint32_t)(lane * 4);
                uint32_t pw = w ^ ((((w >> 5) ^ pm) & 7u) << 2);
                af[kh] = *(const uint4*)(As + ((uint32_t)((wid * 4 + kt) << 7) + pw));
            }
#pragma unroll
            for (int nt = 0; nt < 4; ++nt) {
                uint4 bf = *(const uint4*)(Bs + (size_t)((ktp * 4 + nt) * 32 + lane) * 4);
                mma_tf32(acc[nt], af[0].x, af[0].y, af[0].z, af[0].w, bf.x, bf.y);
                mma_tf32(acc[nt], af[1].x, af[1].y, af[1].z, af[1].w, bf.z, bf.w);
            }
        }
    };

    // prologue: fill chunk 0
    tapsetup(0);
    {
        int cbase = sub * 8;
        float4 u0a = make_float4(0,0,0,0), u0b = u0a, u1a = u0a, u1b = u0a;
        if (valid0) { u0a = *(const float4*)(rowp0 + cbase); u0b = *(const float4*)(rowp0 + cbase + 4); }
        if (valid1) { u1a = *(const float4*)(rowp1 + cbase); u1b = *(const float4*)(rowp1 + cbase + 4); }
        float* A0 = smA[0];
        A0[ast0[0]] = tf32r(u0a.x); A0[ast0[1]] = tf32r(u0a.y);
        A0[ast0[2]] = tf32r(u0a.z); A0[ast0[3]] = tf32r(u0a.w);
        A0[ast0[4]] = tf32r(u0b.x); A0[ast0[5]] = tf32r(u0b.y);
        A0[ast0[6]] = tf32r(u0b.z); A0[ast0[7]] = tf32r(u0b.w);
        A0[ast1[0]] = tf32r(u1a.x); A0[ast1[1]] = tf32r(u1a.y);
        A0[ast1[2]] = tf32r(u1a.z); A0[ast1[3]] = tf32r(u1a.w);
        A0[ast1[4]] = tf32r(u1b.x); A0[ast1[5]] = tf32r(u1b.y);
        A0[ast1[6]] = tf32r(u1b.z); A0[ast1[7]] = tf32r(u1b.w);
    }
    cpasyncB(0, 0);
    CP_WAIT0();
    __syncthreads();

    for (int it = 0; it < NCHUNK; ++it) {
        int s = it & 1;
        int nxt = it + 1;
        bool have = nxt < NCHUNK;
        float4 u0a, u0b, u1a, u1b;
        if (have) {
            if ((nxt & 7) == 0) tapsetup(nxt >> 3);
            int cbase = (nxt & 7) * 32 + sub * 8;
            u0a = make_float4(0,0,0,0); u0b = u0a; u1a = u0a; u1b = u0a;
            if (valid0) { u0a = *(const float4*)(rowp0 + cbase); u0b = *(const float4*)(rowp0 + cbase + 4); }
            if (valid1) { u1a = *(const float4*)(rowp1 + cbase); u1b = *(const float4*)(rowp1 + cbase + 4); }
            cpasyncB(nxt, s ^ 1);
        }
        domma(s);
        if (have) {
            float* An = smA[s ^ 1];
            An[ast0[0]] = tf32r(u0a.x); An[ast0[1]] = tf32r(u0a.y);
            An[ast0[2]] = tf32r(u0a.z); An[ast0[3]] = tf32r(u0a.w);
            An[ast0[4]] = tf32r(u0b.x); An[ast0[5]] = tf32r(u0b.y);
            An[ast0[6]] = tf32r(u0b.z); An[ast0[7]] = tf32r(u0b.w);
            An[ast1[0]] = tf32r(u1a.x); An[ast1[1]] = tf32r(u1a.y);
            An[ast1[2]] = tf32r(u1a.z); An[ast1[3]] = tf32r(u1a.w);
            An[ast1[4]] = tf32r(u1b.x); An[ast1[5]] = tf32r(u1b.y);
            An[ast1[6]] = tf32r(u1b.z); An[ast1[7]] = tf32r(u1b.w);
        }
        CP_WAIT0();
        __syncthreads();
    }

    // ---- epilogue: acc (+bias) -> om_s ----
    {
        int qrow = lane >> 2;
        int qcol = (lane & 3) * 2;
        int row = wid * 16 + qrow;
#pragma unroll
        for (int nt = 0; nt < 4; ++nt) {
            int col = nt * 8 + qcol;
            if (col < 27) {
                float ob = omb[col];
                om_s[row * 28 + col]       = acc[nt][0] + ob;
                om_s[(row + 8) * 28 + col] = acc[nt][2] + ob;
            }
            if (col + 1 < 27) {
                float ob = omb[col + 1];
                om_s[row * 28 + col + 1]       = acc[nt][1] + ob;
                om_s[(row + 8) * 28 + col + 1] = acc[nt][3] + ob;
            }
        }
    }
    __syncthreads();

    // ---- offsets/mask -> g_offmask ----
    if (tid < 64) {
        int px = tid;
        int pp = tile0 + px;
        int ho = (pp % NPIX) / WW;
        int wo = pp % WW;
#pragma unroll
        for (int k = 0; k < 9; ++k) {
            float dy = om_s[px * 28 + 2 * k];
            float dx = om_s[px * 28 + 2 * k + 1];
            float m  = 2.f / (1.f + expf(-om_s[px * 28 + 18 + k]));
            int ky = k / 3, kx = k % 3;
            float py  = (float)(ho - 1 + ky) + dy;
            float pxx = (float)(wo - 1 + kx) + dx;
            g_offmask[pp * 9 + k] = make_float4(py, pxx, m, 0.f);
        }
    }
}

// ---------------------------------------------------------------------------
// Kernel 2: fused bilinear sampling + HMMA tf32 GEMM, software-pipelined.
// 288 CTAs x 512 threads. CTA tile 128 px x 256 F, warp tile 32x64.
// ---------------------------------------------------------------------------
__global__ void __launch_bounds__(512, 1) dcn_mma_kernel(
    const float* __restrict__ x, const float* __restrict__ bias,
    float* __restrict__ out)
{
    extern __shared__ float smem[];
    float* AsArr[2] = { smem,        smem + 4096  };
    float* BsArr[2] = { smem + 8192, smem + 16384 };
    uint32_t sbB = smem_u32(smem + 8192);

    int tid  = threadIdx.x;
    int wid  = tid >> 5;
    int lane = tid & 31;

    int tile0 = blockIdx.x * 128;
    int b = tile0 / NPIX;
    const float* xb = x + (size_t)b * NPIX * CC;

    int spx  = tid >> 2;
    int sub  = tid & 3;
    int pix = tile0 + spx;

    int wm = wid & 3;
    int wn = wid >> 2;

    // A store addresses (invariant)
    uint32_t ast[8];
    {
        int r = spx & 15, smt = spx >> 4;
        uint32_t fb = (uint32_t)((smt * 4 + sub) << 7);
        uint32_t pm = (uint32_t)(((sub << 1) | (smt & 1)) & 7);
#pragma unroll
        for (int cc2 = 0; cc2 < 8; ++cc2) {
            uint32_t t  = (uint32_t)((r & 7) * 4 + (cc2 & 3));
            uint32_t rg = (uint32_t)((r >> 3) + 2 * (cc2 >> 2));
            uint32_t w  = 4u * t + rg;
            ast[cc2] = fb + (w ^ ((((w >> 5) ^ pm) & 7u) << 2));
        }
    }

    float acc[2][8][4];
#pragma unroll
    for (int i = 0; i < 2; ++i)
#pragma unroll
        for (int j = 0; j < 8; ++j)
#pragma unroll
            for (int q = 0; q < 4; ++q) acc[i][j][q] = 0.f;

    float w00 = 0.f, w01 = 0.f, w10 = 0.f, w11 = 0.f;
    uint32_t o00 = 0, o01 = 0, o10 = 0, o11 = 0;

    auto tapsetup = [&](int tap) {
        float4 om = g_offmask[pix * 9 + tap];
        float fy0 = floorf(om.x), fx0 = floorf(om.y);
        int iy0 = (int)fy0, ix0 = (int)fx0;
        float fy = om.x - fy0, fx = om.y - fx0;
        float m = om.z;
        w00 = (1.f - fy) * (1.f - fx) * m;
        w01 = (1.f - fy) * fx * m;
        w10 = fy * (1.f - fx) * m;
        w11 = fy * fx * m;
        if (iy0 < 0  || iy0 >= HH)     { w00 = 0.f; w01 = 0.f; }
        if (iy0 < -1 || iy0 >= HH - 1) { w10 = 0.f; w11 = 0.f; }
        if (ix0 < 0  || ix0 >= WW)     { w00 = 0.f; w10 = 0.f; }
        if (ix0 < -1 || ix0 >= WW - 1) { w01 = 0.f; w11 = 0.f; }
        int y0c = min(max(iy0, 0), HH - 1);
        int y1c = min(max(iy0 + 1, 0), HH - 1);
        int x0c = min(max(ix0, 0), WW - 1);
        int x1c = min(max(ix0 + 1, 0), WW - 1);
        o00 = (uint32_t)((y0c * WW + x0c) * CC);
        o01 = (uint32_t)((y0c * WW + x1c) * CC);
        o10 = (uint32_t)((y1c * WW + x0c) * CC);
        o11 = (uint32_t)((y1c * WW + x1c) * CC);
    };

    auto cpasyncB = [&](int c, int s) {
        const float4* src = (const float4*)g_kernB + (size_t)c * 2048;
        uint32_t bdst = sbB + (uint32_t)s * 32768;
#pragma unroll
        for (int i = 0; i < 4; ++i)
            CP_ASYNC16(bdst + (uint32_t)(tid + i * 512) * 16,
                       (const void*)(src + tid + i * 512));
        CP_COMMIT();
    };

    auto domma_half = [&](int s, int ktp) {
        const float* As = AsArr[s];
        const float* Bs = BsArr[s];
        uint4 af[2][2];
#pragma unroll
        for (int kh = 0; kh < 2; ++kh) {
            int kt = ktp * 2 + kh;
#pragma unroll
            for (int mt = 0; mt < 2; ++mt) {
                int amt = wm * 2 + mt;
                uint32_t pm = (uint32_t)(((kt << 1) | (amt & 1)) & 7);
                uint32_t w = (uint32_t)(lane * 4);
                uint32_t pw = w ^ ((((w >> 5) ^ pm) & 7u) << 2);
                af[kh][mt] = *(const uint4*)(As + ((uint32_t)((amt * 4 + kt) << 7) + pw));
            }
        }
#pragma unroll
        for (int nt = 0; nt < 8; ++nt) {
            int ntg = wn * 8 + nt;
            uint4 bf = *(const uint4*)(Bs + (size_t)((ktp * 32 + ntg) * 32 + lane) * 4);
            mma_tf32(acc[0][nt], af[0][0].x, af[0][0].y, af[0][0].z, af[0][0].w, bf.x, bf.y);
            mma_tf32(acc[1][nt], af[0][1].x, af[0][1].y, af[0][1].z, af[0][1].w, bf.x, bf.y);
            mma_tf32(acc[0][nt], af[1][0].x, af[1][0].y, af[1][0].z, af[1][0].w, bf.z, bf.w);
            mma_tf32(acc[1][nt], af[1][1].x, af[1][1].y, af[1][1].z, af[1][1].w, bf.z, bf.w);
        }
    };

    // prologue: full fill of chunk 0
    tapsetup(0);
    {
        int cbase = sub * 8;
        float va[8];
#pragma unroll
        for (int g = 0; g < 2; ++g) {
            int cg = cbase + g * 4;
            float4 v00 = *(const float4*)(xb + o00 + cg);
            float4 v01 = *(const float4*)(xb + o01 + cg);
            float4 v10 = *(const float4*)(xb + o10 + cg);
            float4 v11 = *(const float4*)(xb + o11 + cg);
            va[g*4+0] = w00*v00.x + w01*v01.x + w10*v10.x + w11*v11.x;
            va[g*4+1] = w00*v00.y + w01*v01.y + w10*v10.y + w11*v11.y;
            va[g*4+2] = w00*v00.z + w01*v01.z + w10*v10.z + w11*v11.z;
            va[g*4+3] = w00*v00.w + w01*v01.w + w10*v10.w + w11*v11.w;
        }
        float* A0 = AsArr[0];
#pragma unroll
        for (int cc2 = 0; cc2 < 8; ++cc2) A0[ast[cc2]] = tf32r(va[cc2]);
    }
    cpasyncB(0, 0);
    CP_WAIT0();
    __syncthreads();

    for (int it = 0; it < NCHUNK; ++it) {
        int s = it & 1;
        int nxt = it + 1;
        bool have = nxt < NCHUNK;
        int cbase = 0;
        float4 ca0, ca1, cb0, cb1;
        float va[8];

        if (have) {
            if ((nxt & 7) == 0) tapsetup(nxt >> 3);
            cbase = (nxt & 7) * 32 + sub * 8;
            // corners 00, 01
            ca0 = *(const float4*)(xb + o00 + cbase);
            ca1 = *(const float4*)(xb + o00 + cbase + 4);
            cb0 = *(const float4*)(xb + o01 + cbase);
            cb1 = *(const float4*)(xb + o01 + cbase + 4);
            cpasyncB(nxt, s ^ 1);
        }

        domma_half(s, 0);

        if (have) {
            va[0] = w00*ca0.x + w01*cb0.x;
            va[1] = w00*ca0.y + w01*cb0.y;
            va[2] = w00*ca0.z + w01*cb0.z;
            va[3] = w00*ca0.w + w01*cb0.w;
            va[4] = w00*ca1.x + w01*cb1.x;
            va[5] = w00*ca1.y + w01*cb1.y;
            va[6] = w00*ca1.z + w01*cb1.z;
            va[7] = w00*ca1.w + w01*cb1.w;
            // corners 10, 11
            ca0 = *(const float4*)(xb + o10 + cbase);
            ca1 = *(const float4*)(xb + o10 + cbase + 4);
            cb0 = *(const float4*)(xb + o11 + cbase);
            cb1 = *(const float4*)(xb + o11 + cbase + 4);
        }

        domma_half(s, 1);

        if (have) {
            va[0] += w10*ca0.x + w11*cb0.x;
            va[1] += w10*ca0.y + w11*cb0.y;
            va[2] += w10*ca0.z + w11*cb0.z;
            va[3] += w10*ca0.w + w11*cb0.w;
            va[4] += w10*ca1.x + w11*cb1.x;
            va[5] += w10*ca1.y + w11*cb1.y;
            va[6] += w10*ca1.z + w11*cb1.z;
            va[7] += w10*ca1.w + w11*cb1.w;
            float* An = AsArr[s ^ 1];
#pragma unroll
            for (int cc2 = 0; cc2 < 8; ++cc2) An[ast[cc2]] = tf32r(va[cc2]);
        }

        CP_WAIT0();
        __syncthreads();
    }

    // ---- epilogue: acc -> global with bias ----
    {
        int col0 = wn * 64;
        int qrow = lane >> 2;
        int qcol = (lane & 3) * 2;
        float2 bv[8];
#pragma unroll
        for (int nt = 0; nt < 8; ++nt)
            bv[nt] = *(const float2*)(bias + col0 + nt * 8 + qcol);
#pragma unroll
        for (int mt = 0; mt < 2; ++mt) {
            int row = tile0 + wm * 32 + mt * 16 + qrow;
#pragma unroll
            for (int nt = 0; nt < 8; ++nt) {
                int col = col0 + nt * 8 + qcol;
                float2 lo, hi;
                lo.x = acc[mt][nt][0] + bv[nt].x;
                lo.y = acc[mt][nt][1] + bv[nt].y;
                hi.x = acc[mt][nt][2] + bv[nt].x;
                hi.y = acc[mt][nt][3] + bv[nt].y;
                *(float2*)(out + (size_t)row * FF + col)       = lo;
                *(float2*)(out + (size_t)(row + 8) * FF + col) = hi;
            }
        }
    }
}

#define SMEM_BYTES (24576 * 4)   // 96 KB

extern "C" void kernel_launch(void* const* d_in, const int* in_sizes, int n_in,
                              void* d_out, int out_size)
{
    const float* x    = (const float*)d_in[0];  // [4,96,96,256]
    const float* omk  = (const float*)d_in[1];  // [3,3,256,27]
    const float* omb  = (const float*)d_in[2];  // [27]
    const float* kern = (const float*)d_in[3];  // [2304,256]
    const float* bias = (const float*)d_in[4];  // [256]
    float* out = (float*)d_out;                 // [36864,256]

    cudaFuncSetAttribute(dcn_mma_kernel,
                         cudaFuncAttributeMaxDynamicSharedMemorySize, SMEM_BYTES);

    transpose_kernel<<<576, 256>>>(kern);
    om_transpose_kernel<<<72, 256>>>(omk);
    om_mma_kernel<<<TOTPIX / 64, 128>>>(x, omb);
    dcn_mma_kernel<<<TOTPIX / 128, 512, SMEM_BYTES>>>(x, bias, out);
}

// round 6
// speedup vs baseline: 4.8536x; 1.6492x over previous
#include <cuda_runtime.h>
#include <cuda_fp16.h>
#include <math.h>
#include <stdint.h>

#define HH 96
#define WW 96
#define CC 256
#define FF 256
#define BB 4
#define NPIX (HH*WW)        // 9216
#define TOTPIX (BB*NPIX)    // 36864
#define NCHUNK 72           // 2304 / 32

// scratch: per (pixel, tap): (py, px, mask, 0)
__device__ float4 g_offmask[TOTPIX * 9];
// main weights fp16 fragment-packed: [chunk72][ks2][ntile32][lane32][reg2] (half2 as u32)
__device__ uint32_t g_kernH[NCHUNK * 2 * 32 * 32 * 2];
// om weights tf32 fragment order: [chunk72][ktp2][ntile4][lane32][4] (n>=27 zero)
__device__ float g_omkB[NCHUNK * 2 * 4 * 32 * 4];

__device__ __forceinline__ float tf32r(float f) {
    float r;
    asm("cvt.rna.tf32.f32 %0, %1;" : "=f"(r) : "f"(f));
    return r;
}
__device__ __forceinline__ uint32_t smem_u32(const void* p) {
    uint32_t a;
    asm("{ .reg .u64 t; cvta.to.shared.u64 t, %1; cvt.u32.u64 %0, t; }" : "=r"(a) : "l"(p));
    return a;
}

#define CP_ASYNC16(dst, src) \
    asm volatile("cp.async.cg.shared.global [%0], [%1], 16;" :: "r"(dst), "l"(src) : "memory")
#define CP_COMMIT() asm volatile("cp.async.commit_group;" ::: "memory")
#define CP_WAIT0()  asm volatile("cp.async.wait_group 0;" ::: "memory")

__device__ __forceinline__ void mma_tf32(
    float* d, uint32_t a0, uint32_t a1, uint32_t a2, uint32_t a3,
    uint32_t b0, uint32_t b1)
{
    asm volatile(
        "mma.sync.aligned.m16n8k8.row.col.f32.tf32.tf32.f32 "
        "{%0,%1,%2,%3}, {%4,%5,%6,%7}, {%8,%9}, {%0,%1,%2,%3};"
        : "+f"(d[0]), "+f"(d[1]), "+f"(d[2]), "+f"(d[3])
        : "r"(a0), "r"(a1), "r"(a2), "r"(a3), "r"(b0), "r"(b1));
}
__device__ __forceinline__ void mma_f16(
    float* d, uint4 a, uint2 b)
{
    asm volatile(
        "mma.sync.aligned.m16n8k16.row.col.f32.f16.f16.f32 "
        "{%0,%1,%2,%3}, {%4,%5,%6,%7}, {%8,%9}, {%0,%1,%2,%3};"
        : "+f"(d[0]), "+f"(d[1]), "+f"(d[2]), "+f"(d[3])
        : "r"(a.x), "r"(a.y), "r"(a.z), "r"(a.w), "r"(b.x), "r"(b.y));
}

// ---------------------------------------------------------------------------
// Kernel 0a: main weight pack (fp16 m16n8k16 B-fragment order).
// idx -> (c, ks, nt, lane, reg): n = nt*8 + lane>>2; k = c*32+ks*16+(lane&3)*2+reg*8
// ---------------------------------------------------------------------------
__global__ void __launch_bounds__(256) transpose_kernel(const float* __restrict__ kern)
{
    int idx = blockIdx.x * 256 + threadIdx.x;    // 0 .. 294911
    int reg  = idx & 1;
    int lane = (idx >> 1) & 31;
    int nt   = (idx >> 6) & 31;
    int ks   = (idx >> 11) & 1;
    int c    = idx >> 12;
    int n = nt * 8 + (lane >> 2);
    int k = c * 32 + ks * 16 + (lane & 3) * 2 + reg * 8;
    __half2 h = __floats2half2_rn(kern[k * 256 + n], kern[(k + 1) * 256 + n]);
    g_kernH[idx] = *(uint32_t*)&h;
}

// ---------------------------------------------------------------------------
// Kernel 0b: om weight shuffle (tf32 fragment order), N padded to 32.
// ---------------------------------------------------------------------------
__global__ void __launch_bounds__(256) om_transpose_kernel(const float* __restrict__ omk)
{
    int idx = blockIdx.x * 256 + threadIdx.x;    // 0 .. 18431
    int t   = idx & 31;
    int nt  = (idx >> 5) & 3;
    int ktp = (idx >> 7) & 1;
    int ch  = idx >> 8;
    int n = nt * 8 + (t >> 2);
    int kbase = ch * 32 + ktp * 16 + (t & 3);
    float4 v = make_float4(0.f, 0.f, 0.f, 0.f);
    if (n < 27) {
        v.x = tf32r(omk[(kbase + 0)  * 27 + n]);
        v.y = tf32r(omk[(kbase + 4)  * 27 + n]);
        v.z = tf32r(omk[(kbase + 8)  * 27 + n]);
        v.w = tf32r(omk[(kbase + 12) * 27 + n]);
    }
    ((float4*)g_omkB)[idx] = v;
}

// ---------------------------------------------------------------------------
// Kernel 1: om conv as HMMA tf32 GEMM. 576 CTAs x 128 threads (R5, proven).
// ---------------------------------------------------------------------------
__global__ void __launch_bounds__(128) om_mma_kernel(
    const float* __restrict__ x, const float* __restrict__ omb)
{
    __shared__ float smA[2][2048];
    __shared__ float smB[2][1024];
    __shared__ float om_s[64 * 28];
    uint32_t sbB = smem_u32(&smB[0][0]);

    int tid  = threadIdx.x;
    int wid  = tid >> 5;
    int lane = tid & 31;

    int tile0 = blockIdx.x * 64;
    int b = tile0 / NPIX;
    const float* xb = x + (size_t)b * NPIX * CC;

    int sub  = tid & 3;
    int px0  = tid >> 2;
    int px1  = px0 + 32;
    int pp0  = tile0 + px0;
    int pp1  = tile0 + px1;
    int ho0  = (pp0 % NPIX) / WW, wo0 = pp0 % WW;
    int ho1  = (pp1 % NPIX) / WW, wo1 = pp1 % WW;

    uint32_t ast0[8], ast1[8];
    {
        int r0 = px0 & 15, smt0 = px0 >> 4;
        int r1 = px1 & 15, smt1 = px1 >> 4;
        uint32_t fb0 = (uint32_t)((smt0 * 4 + sub) << 7);
        uint32_t fb1 = (uint32_t)((smt1 * 4 + sub) << 7);
        uint32_t pm0 = (uint32_t)(((sub << 1) | (smt0 & 1)) & 7);
        uint32_t pm1 = (uint32_t)(((sub << 1) | (smt1 & 1)) & 7);
#pragma unroll
        for (int cc2 = 0; cc2 < 8; ++cc2) {
            uint32_t t0  = (uint32_t)((r0 & 7) * 4 + (cc2 & 3));
            uint32_t rg0 = (uint32_t)((r0 >> 3) + 2 * (cc2 >> 2));
            uint32_t w0  = 4u * t0 + rg0;
            ast0[cc2] = fb0 + (w0 ^ ((((w0 >> 5) ^ pm0) & 7u) << 2));
            uint32_t t1  = (uint32_t)((r1 & 7) * 4 + (cc2 & 3));
            uint32_t rg1 = (uint32_t)((r1 >> 3) + 2 * (cc2 >> 2));
            uint32_t w1  = 4u * t1 + rg1;
            ast1[cc2] = fb1 + (w1 ^ ((((w1 >> 5) ^ pm1) & 7u) << 2));
        }
    }

    float acc[4][4];
#pragma unroll
    for (int j = 0; j < 4; ++j)
#pragma unroll
        for (int q = 0; q < 4; ++q) acc[j][q] = 0.f;

    const float* rowp0 = xb; bool valid0 = false;
    const float* rowp1 = xb; bool valid1 = false;

    auto tapsetup = [&](int tap) {
        int ky = tap / 3, kx = tap % 3;
        int y0 = ho0 - 1 + ky, x0 = wo0 - 1 + kx;
        valid0 = (y0 >= 0 && y0 < HH && x0 >= 0 && x0 < WW);
        rowp0 = xb + (size_t)(y0 * WW + x0) * CC;
        int y1 = ho1 - 1 + ky, x1 = wo1 - 1 + kx;
        valid1 = (y1 >= 0 && y1 < HH && x1 >= 0 && x1 < WW);
        rowp1 = xb + (size_t)(y1 * WW + x1) * CC;
    };

    auto cpasyncB = [&](int c, int s) {
        const float4* src = (const float4*)g_omkB + (size_t)c * 256;
        uint32_t bdst = sbB + (uint32_t)s * 4096;
#pragma unroll
        for (int i = 0; i < 2; ++i)
            CP_ASYNC16(bdst + (uint32_t)(tid + i * 128) * 16,
                       (const void*)(src + tid + i * 128));
        CP_COMMIT();
    };

    auto domma = [&](int s) {
        const float* As = smA[s];
        const float* Bs = smB[s];
#pragma unroll
        for (int ktp = 0; ktp < 2; ++ktp) {
            uint4 af[2];
#pragma unroll
            for (int kh = 0; kh < 2; ++kh) {
                int kt = ktp * 2 + kh;
                uint32_t pm = (uint32_t)(((kt << 1) | (wid & 1)) & 7);
                uint32_t w = (uint32_t)(lane * 4);
                uint32_t pw = w ^ ((((w >> 5) ^ pm) & 7u) << 2);
                af[kh] = *(const uint4*)(As + ((uint32_t)((wid * 4 + kt) << 7) + pw));
            }
#pragma unroll
            for (int nt = 0; nt < 4; ++nt) {
                uint4 bf = *(const uint4*)(Bs + (size_t)((ktp * 4 + nt) * 32 + lane) * 4);
                mma_tf32(acc[nt], af[0].x, af[0].y, af[0].z, af[0].w, bf.x, bf.y);
                mma_tf32(acc[nt], af[1].x, af[1].y, af[1].z, af[1].w, bf.z, bf.w);
            }
        }
    };

    tapsetup(0);
    {
        int cbase = sub * 8;
        float4 u0a = make_float4(0,0,0,0), u0b = u0a, u1a = u0a, u1b = u0a;
        if (valid0) { u0a = *(const float4*)(rowp0 + cbase); u0b = *(const float4*)(rowp0 + cbase + 4); }
        if (valid1) { u1a = *(const float4*)(rowp1 + cbase); u1b = *(const float4*)(rowp1 + cbase + 4); }
        float* A0 = smA[0];
        A0[ast0[0]] = tf32r(u0a.x); A0[ast0[1]] = tf32r(u0a.y);
        A0[ast0[2]] = tf32r(u0a.z); A0[ast0[3]] = tf32r(u0a.w);
        A0[ast0[4]] = tf32r(u0b.x); A0[ast0[5]] = tf32r(u0b.y);
        A0[ast0[6]] = tf32r(u0b.z); A0[ast0[7]] = tf32r(u0b.w);
        A0[ast1[0]] = tf32r(u1a.x); A0[ast1[1]] = tf32r(u1a.y);
        A0[ast1[2]] = tf32r(u1a.z); A0[ast1[3]] = tf32r(u1a.w);
        A0[ast1[4]] = tf32r(u1b.x); A0[ast1[5]] = tf32r(u1b.y);
        A0[ast1[6]] = tf32r(u1b.z); A0[ast1[7]] = tf32r(u1b.w);
    }
    cpasyncB(0, 0);
    CP_WAIT0();
    __syncthreads();

    for (int it = 0; it < NCHUNK; ++it) {
        int s = it & 1;
        int nxt = it + 1;
        bool have = nxt < NCHUNK;
        float4 u0a, u0b, u1a, u1b;
        if (have) {
            if ((nxt & 7) == 0) tapsetup(nxt >> 3);
            int cbase = (nxt & 7) * 32 + sub * 8;
            u0a = make_float4(0,0,0,0); u0b = u0a; u1a = u0a; u1b = u0a;
            if (valid0) { u0a = *(const float4*)(rowp0 + cbase); u0b = *(const float4*)(rowp0 + cbase + 4); }
            if (valid1) { u1a = *(const float4*)(rowp1 + cbase); u1b = *(const float4*)(rowp1 + cbase + 4); }
            cpasyncB(nxt, s ^ 1);
        }
        domma(s);
        if (have) {
            float* An = smA[s ^ 1];
            An[ast0[0]] = tf32r(u0a.x); An[ast0[1]] = tf32r(u0a.y);
            An[ast0[2]] = tf32r(u0a.z); An[ast0[3]] = tf32r(u0a.w);
            An[ast0[4]] = tf32r(u0b.x); An[ast0[5]] = tf32r(u0b.y);
            An[ast0[6]] = tf32r(u0b.z); An[ast0[7]] = tf32r(u0b.w);
            An[ast1[0]] = tf32r(u1a.x); An[ast1[1]] = tf32r(u1a.y);
            An[ast1[2]] = tf32r(u1a.z); An[ast1[3]] = tf32r(u1a.w);
            An[ast1[4]] = tf32r(u1b.x); An[ast1[5]] = tf32r(u1b.y);
            An[ast1[6]] = tf32r(u1b.z); An[ast1[7]] = tf32r(u1b.w);
        }
        CP_WAIT0();
        __syncthreads();
    }

    {
        int qrow = lane >> 2;
        int qcol = (lane & 3) * 2;
        int row = wid * 16 + qrow;
#pragma unroll
        for (int nt = 0; nt < 4; ++nt) {
            int col = nt * 8 + qcol;
            if (col < 27) {
                float ob = omb[col];
                om_s[row * 28 + col]       = acc[nt][0] + ob;
                om_s[(row + 8) * 28 + col] = acc[nt][2] + ob;
            }
            if (col + 1 < 27) {
                float ob = omb[col + 1];
                om_s[row * 28 + col + 1]       = acc[nt][1] + ob;
                om_s[(row + 8) * 28 + col + 1] = acc[nt][3] + ob;
            }
        }
    }
    __syncthreads();

    if (tid < 64) {
        int px = tid;
        int pp = tile0 + px;
        int ho = (pp % NPIX) / WW;
        int wo = pp % WW;
#pragma unroll
        for (int k = 0; k < 9; ++k) {
            float dy = om_s[px * 28 + 2 * k];
            float dx = om_s[px * 28 + 2 * k + 1];
            float m  = 2.f / (1.f + expf(-om_s[px * 28 + 18 + k]));
            int ky = k / 3, kx = k % 3;
            float py  = (float)(ho - 1 + ky) + dy;
            float pxx = (float)(wo - 1 + kx) + dx;
            g_offmask[pp * 9 + k] = make_float4(py, pxx, m, 0.f);
        }
    }
}

// ---------------------------------------------------------------------------
// Kernel 2: fused bilinear sampling + HMMA fp16 GEMM (m16n8k16).
// 288 CTAs x 512 threads. CTA tile 128 px x 256 F, warp tile 32x64.
// Sampler: lane = (px-quad)*8 + ch-oct; 2 pixel rounds per chunk.
// A smem: per (amt, ks) blocks of 132 u32 (fragment layout, uint4 consumer).
// ---------------------------------------------------------------------------
#define A_STAGE 2112                 // u32 per A stage (16 blocks * 132)
#define B_STAGE 4096                 // u32 per B stage (16 KB)
#define SMEM_U32 (2*A_STAGE + 2*B_STAGE)

__global__ void __launch_bounds__(512, 1) dcn_mma_kernel(
    const float* __restrict__ x, const float* __restrict__ bias,
    float* __restrict__ out)
{
    extern __shared__ uint32_t sm[];
    uint32_t* AsArr[2] = { sm, sm + A_STAGE };
    uint32_t* BsArr[2] = { sm + 2*A_STAGE, sm + 2*A_STAGE + B_STAGE };
    uint32_t sbB = smem_u32(sm + 2*A_STAGE);

    int tid  = threadIdx.x;
    int wid  = tid >> 5;
    int lane = tid & 31;

    int tile0 = blockIdx.x * 128;
    int b = tile0 / NPIX;
    const float* xb = x + (size_t)b * NPIX * CC;

    // sampler identity
    int o8  = lane & 7;                 // channel oct (4 ch)
    int pxq = lane >> 3;                // 0..3
    int pxl[2] = { wid * 8 + pxq, wid * 8 + 4 + pxq };   // local pixel per round
    int sks = o8 >> 2;                  // kstep this thread's channels fall in

    // A-fragment store base (j=0) per round
    uint32_t ast[2];
#pragma unroll
    for (int q = 0; q < 2; ++q) {
        int r   = pxl[q] & 15;
        int amt = pxl[q] >> 4;
        uint32_t lf  = (uint32_t)((r & 7) * 4 + (2 * (o8 & 1)));   // lane_frag j=0
        uint32_t reg = (uint32_t)(((r & 15) >= 8 ? 1 : 0) + 2 * ((o8 >> 1) & 1));
        ast[q] = (uint32_t)(amt * 2 + sks) * 132u + lf * 4u + reg;
    }

    // gemm identity
    int wm = wid & 3;
    int wn = wid >> 2;

    float acc[2][8][4];
#pragma unroll
    for (int i = 0; i < 2; ++i)
#pragma unroll
        for (int j = 0; j < 8; ++j)
#pragma unroll
            for (int q = 0; q < 4; ++q) acc[i][j][q] = 0.f;

    // per-round sampling state
    float wgt[2][4];
    uint32_t ofs[2][4];

    auto tapsetup = [&](int tap) {
#pragma unroll
        for (int q = 0; q < 2; ++q) {
            float4 om = g_offmask[(size_t)(tile0 + pxl[q]) * 9 + tap];
            float fy0 = floorf(om.x), fx0 = floorf(om.y);
            int iy0 = (int)fy0, ix0 = (int)fx0;
            float fy = om.x - fy0, fx = om.y - fx0;
            float m = om.z;
            float w00 = (1.f - fy) * (1.f - fx) * m;
            float w01 = (1.f - fy) * fx * m;
            float w10 = fy * (1.f - fx) * m;
            float w11 = fy * fx * m;
            if (iy0 < 0  || iy0 >= HH)     { w00 = 0.f; w01 = 0.f; }
            if (iy0 < -1 || iy0 >= HH - 1) { w10 = 0.f; w11 = 0.f; }
            if (ix0 < 0  || ix0 >= WW)     { w00 = 0.f; w10 = 0.f; }
            if (ix0 < -1 || ix0 >= WW - 1) { w01 = 0.f; w11 = 0.f; }
            int y0c = min(max(iy0, 0), HH - 1);
            int y1c = min(max(iy0 + 1, 0), HH - 1);
            int x0c = min(max(ix0, 0), WW - 1);
            int x1c = min(max(ix0 + 1, 0), WW - 1);
            wgt[q][0] = w00; wgt[q][1] = w01; wgt[q][2] = w10; wgt[q][3] = w11;
            ofs[q][0] = (uint32_t)((y0c * WW + x0c) * CC);
            ofs[q][1] = (uint32_t)((y0c * WW + x1c) * CC);
            ofs[q][2] = (uint32_t)((y1c * WW + x0c) * CC);
            ofs[q][3] = (uint32_t)((y1c * WW + x1c) * CC);
        }
    };

    auto cpasyncB = [&](int c, int s) {
        const float4* src = (const float4*)g_kernH + (size_t)c * 1024;
        uint32_t bdst = sbB + (uint32_t)s * (B_STAGE * 4);
#pragma unroll
        for (int i = 0; i < 2; ++i)
            CP_ASYNC16(bdst + (uint32_t)(tid + i * 512) * 16,
                       (const void*)(src + tid + i * 512));
        CP_COMMIT();
    };

    auto domma = [&](int s, int ks) {
        const uint32_t* As = AsArr[s];
        const uint32_t* Bs = BsArr[s];
        uint4 af[2];
#pragma unroll
        for (int mt = 0; mt < 2; ++mt) {
            int amt = wm * 2 + mt;
            af[mt] = *(const uint4*)(As + (uint32_t)(amt * 2 + ks) * 132u + (uint32_t)lane * 4u);
        }
#pragma unroll
        for (int nt = 0; nt < 8; ++nt) {
            int ntg = wn * 8 + nt;
            uint2 bf = *(const uint2*)(Bs + ((uint32_t)(ks * 32 + ntg) * 32 + lane) * 2u);
            mma_f16(acc[0][nt], af[0], bf);
            mma_f16(acc[1][nt], af[1], bf);
        }
    };

    // prologue: fill chunk 0
    tapsetup(0);
#pragma unroll
    for (int q = 0; q < 2; ++q) {
        const float* base = xb + o8 * 4;
        float4 v0 = *(const float4*)(base + ofs[q][0]);
        float4 v1 = *(const float4*)(base + ofs[q][1]);
        float4 v2 = *(const float4*)(base + ofs[q][2]);
        float4 v3 = *(const float4*)(base + ofs[q][3]);
        float r0 = wgt[q][0]*v0.x + wgt[q][1]*v1.x + wgt[q][2]*v2.x + wgt[q][3]*v3.x;
        float r1 = wgt[q][0]*v0.y + wgt[q][1]*v1.y + wgt[q][2]*v2.y + wgt[q][3]*v3.y;
        float r2 = wgt[q][0]*v0.z + wgt[q][1]*v1.z + wgt[q][2]*v2.z + wgt[q][3]*v3.z;
        float r3 = wgt[q][0]*v0.w + wgt[q][1]*v1.w + wgt[q][2]*v2.w + wgt[q][3]*v3.w;
        __half2 h0 = __floats2half2_rn(r0, r1);
        __half2 h1 = __floats2half2_rn(r2, r3);
        AsArr[0][ast[q]]     = *(uint32_t*)&h0;
        AsArr[0][ast[q] + 4] = *(uint32_t*)&h1;
    }
    cpasyncB(0, 0);
    CP_WAIT0();
    __syncthreads();

    for (int it = 0; it < NCHUNK; ++it) {
        int s = it & 1;
        int nxt = it + 1;
        bool have = nxt < NCHUNK;
        uint32_t cho = 0;
        float4 v0, v1, v2, v3;

        if (have) {
            if ((nxt & 7) == 0) tapsetup(nxt >> 3);
            cho = (uint32_t)((nxt & 7) * 32 + o8 * 4);
            // round 0 corner loads
            v0 = *(const float4*)(xb + ofs[0][0] + cho);
            v1 = *(const float4*)(xb + ofs[0][1] + cho);
            v2 = *(const float4*)(xb + ofs[0][2] + cho);
            v3 = *(const float4*)(xb + ofs[0][3] + cho);
            cpasyncB(nxt, s ^ 1);
        }

        domma(s, 0);

        if (have) {
            float r0 = wgt[0][0]*v0.x + wgt[0][1]*v1.x + wgt[0][2]*v2.x + wgt[0][3]*v3.x;
            float r1 = wgt[0][0]*v0.y + wgt[0][1]*v1.y + wgt[0][2]*v2.y + wgt[0][3]*v3.y;
            float r2 = wgt[0][0]*v0.z + wgt[0][1]*v1.z + wgt[0][2]*v2.z + wgt[0][3]*v3.z;
            float r3 = wgt[0][0]*v0.w + wgt[0][1]*v1.w + wgt[0][2]*v2.w + wgt[0][3]*v3.w;
            __half2 h0 = __floats2half2_rn(r0, r1);
            __half2 h1 = __floats2half2_rn(r2, r3);
            uint32_t* An = AsArr[s ^ 1];
            An[ast[0]]     = *(uint32_t*)&h0;
            An[ast[0] + 4] = *(uint32_t*)&h1;
            // round 1 corner loads
            v0 = *(const float4*)(xb + ofs[1][0] + cho);
            v1 = *(const float4*)(xb + ofs[1][1] + cho);
            v2 = *(const float4*)(xb + ofs[1][2] + cho);
            v3 = *(const float4*)(xb + ofs[1][3] + cho);
        }

        domma(s, 1);

        if (have) {
            float r0 = wgt[1][0]*v0.x + wgt[1][1]*v1.x + wgt[1][2]*v2.x + wgt[1][3]*v3.x;
            float r1 = wgt[1][0]*v0.y + wgt[1][1]*v1.y + wgt[1][2]*v2.y + wgt[1][3]*v3.y;
            float r2 = wgt[1][0]*v0.z + wgt[1][1]*v1.z + wgt[1][2]*v2.z + wgt[1][3]*v3.z;
            float r3 = wgt[1][0]*v0.w + wgt[1][1]*v1.w + wgt[1][2]*v2.w + wgt[1][3]*v3.w;
            __half2 h0 = __floats2half2_rn(r0, r1);
            __half2 h1 = __floats2half2_rn(r2, r3);
            uint32_t* An = AsArr[s ^ 1];
            An[ast[1]]     = *(uint32_t*)&h0;
            An[ast[1] + 4] = *(uint32_t*)&h1;
        }

        CP_WAIT0();
        __syncthreads();
    }

    // ---- epilogue: acc -> global with bias ----
    {
        int col0 = wn * 64;
        int qrow = lane >> 2;
        int qcol = (lane & 3) * 2;
        float2 bv[8];
#pragma unroll
        for (int nt = 0; nt < 8; ++nt)
            bv[nt] = *(const float2*)(bias + col0 + nt * 8 + qcol);
#pragma unroll
        for (int mt = 0; mt < 2; ++mt) {
            int row = tile0 + wm * 32 + mt * 16 + qrow;
#pragma unroll
            for (int nt = 0; nt < 8; ++nt) {
                int col = col0 + nt * 8 + qcol;
                float2 lo, hi;
                lo.x = acc[mt][nt][0] + bv[nt].x;
                lo.y = acc[mt][nt][1] + bv[nt].y;
                hi.x = acc[mt][nt][2] + bv[nt].x;
                hi.y = acc[mt][nt][3] + bv[nt].y;
                *(float2*)(out + (size_t)row * FF + col)       = lo;
                *(float2*)(out + (size_t)(row + 8) * FF + col) = hi;
            }
        }
    }
}

extern "C" void kernel_launch(void* const* d_in, const int* in_sizes, int n_in,
                              void* d_out, int out_size)
{
    const float* x    = (const float*)d_in[0];  // [4,96,96,256]
    const float* omk  = (const float*)d_in[1];  // [3,3,256,27]
    const float* omb  = (const float*)d_in[2];  // [27]
    const float* kern = (const float*)d_in[3];  // [2304,256]
    const float* bias = (const float*)d_in[4];  // [256]
    float* out = (float*)d_out;                 // [36864,256]

    cudaFuncSetAttribute(dcn_mma_kernel,
                         cudaFuncAttributeMaxDynamicSharedMemorySize, SMEM_U32 * 4);

    transpose_kernel<<<1152, 256>>>(kern);
    om_transpose_kernel<<<72, 256>>>(omk);
    om_mma_kernel<<<TOTPIX / 64, 128>>>(x, omb);
    dcn_mma_kernel<<<TOTPIX / 128, 512, SMEM_U32 * 4>>>(x, bias, out);
}

// round 7
// speedup vs baseline: 4.9846x; 1.0270x over previous
#include <cuda_runtime.h>
#include <cuda_fp16.h>
#include <math.h>
#include <stdint.h>

#define HH 96
#define WW 96
#define CC 256
#define FF 256
#define BB 4
#define NPIX (HH*WW)        // 9216
#define TOTPIX (BB*NPIX)    // 36864
#define NCHUNK 72           // 2304 / 32

// scratch: per (pixel, tap): (py, px, mask, 0)
__device__ float4 g_offmask[TOTPIX * 9];
// main weights fp16 fragment-packed: [chunk72][ks2][ntile32][lane32][reg2] (half2 as u32)
__device__ uint32_t g_kernH[NCHUNK * 2 * 32 * 32 * 2];
// om weights tf32 fragment order: [chunk72][ktp2][ntile4][lane32][4] (n>=27 zero)
__device__ float g_omkB[NCHUNK * 2 * 4 * 32 * 4];

__device__ __forceinline__ float tf32r(float f) {
    float r;
    asm("cvt.rna.tf32.f32 %0, %1;" : "=f"(r) : "f"(f));
    return r;
}
__device__ __forceinline__ uint32_t smem_u32(const void* p) {
    uint32_t a;
    asm("{ .reg .u64 t; cvta.to.shared.u64 t, %1; cvt.u32.u64 %0, t; }" : "=r"(a) : "l"(p));
    return a;
}

#define CP_ASYNC16(dst, src) \
    asm volatile("cp.async.cg.shared.global [%0], [%1], 16;" :: "r"(dst), "l"(src) : "memory")
#define CP_COMMIT() asm volatile("cp.async.commit_group;" ::: "memory")
#define CP_WAIT0()  asm volatile("cp.async.wait_group 0;" ::: "memory")

__device__ __forceinline__ void mma_tf32(
    float* d, uint32_t a0, uint32_t a1, uint32_t a2, uint32_t a3,
    uint32_t b0, uint32_t b1)
{
    asm volatile(
        "mma.sync.aligned.m16n8k8.row.col.f32.tf32.tf32.f32 "
        "{%0,%1,%2,%3}, {%4,%5,%6,%7}, {%8,%9}, {%0,%1,%2,%3};"
        : "+f"(d[0]), "+f"(d[1]), "+f"(d[2]), "+f"(d[3])
        : "r"(a0), "r"(a1), "r"(a2), "r"(a3), "r"(b0), "r"(b1));
}
__device__ __forceinline__ void mma_f16(
    float* d, uint4 a, uint2 b)
{
    asm volatile(
        "mma.sync.aligned.m16n8k16.row.col.f32.f16.f16.f32 "
        "{%0,%1,%2,%3}, {%4,%5,%6,%7}, {%8,%9}, {%0,%1,%2,%3};"
        : "+f"(d[0]), "+f"(d[1]), "+f"(d[2]), "+f"(d[3])
        : "r"(a.x), "r"(a.y), "r"(a.z), "r"(a.w), "r"(b.x), "r"(b.y));
}

// ---------------------------------------------------------------------------
// Kernel 0a: main weight pack (fp16 m16n8k16 B-fragment order).
// ---------------------------------------------------------------------------
__global__ void __launch_bounds__(256) transpose_kernel(const float* __restrict__ kern)
{
    int idx = blockIdx.x * 256 + threadIdx.x;    // 0 .. 294911
    int reg  = idx & 1;
    int lane = (idx >> 1) & 31;
    int nt   = (idx >> 6) & 31;
    int ks   = (idx >> 11) & 1;
    int c    = idx >> 12;
    int n = nt * 8 + (lane >> 2);
    int k = c * 32 + ks * 16 + (lane & 3) * 2 + reg * 8;
    __half2 h = __floats2half2_rn(kern[k * 256 + n], kern[(k + 1) * 256 + n]);
    g_kernH[idx] = *(uint32_t*)&h;
}

// ---------------------------------------------------------------------------
// Kernel 0b: om weight shuffle (tf32 fragment order), N padded to 32.
// ---------------------------------------------------------------------------
__global__ void __launch_bounds__(256) om_transpose_kernel(const float* __restrict__ omk)
{
    int idx = blockIdx.x * 256 + threadIdx.x;    // 0 .. 18431
    int t   = idx & 31;
    int nt  = (idx >> 5) & 3;
    int ktp = (idx >> 7) & 1;
    int ch  = idx >> 8;
    int n = nt * 8 + (t >> 2);
    int kbase = ch * 32 + ktp * 16 + (t & 3);
    float4 v = make_float4(0.f, 0.f, 0.f, 0.f);
    if (n < 27) {
        v.x = tf32r(omk[(kbase + 0)  * 27 + n]);
        v.y = tf32r(omk[(kbase + 4)  * 27 + n]);
        v.z = tf32r(omk[(kbase + 8)  * 27 + n]);
        v.w = tf32r(omk[(kbase + 12) * 27 + n]);
    }
    ((float4*)g_omkB)[idx] = v;
}

// ---------------------------------------------------------------------------
// Kernel 1: om conv as HMMA tf32 GEMM. 576 CTAs x 128 threads (proven).
// ---------------------------------------------------------------------------
__global__ void __launch_bounds__(128) om_mma_kernel(
    const float* __restrict__ x, const float* __restrict__ omb)
{
    __shared__ float smA[2][2048];
    __shared__ float smB[2][1024];
    __shared__ float om_s[64 * 28];
    uint32_t sbB = smem_u32(&smB[0][0]);

    int tid  = threadIdx.x;
    int wid  = tid >> 5;
    int lane = tid & 31;

    int tile0 = blockIdx.x * 64;
    int b = tile0 / NPIX;
    const float* xb = x + (size_t)b * NPIX * CC;

    int sub  = tid & 3;
    int px0  = tid >> 2;
    int px1  = px0 + 32;
    int pp0  = tile0 + px0;
    int pp1  = tile0 + px1;
    int ho0  = (pp0 % NPIX) / WW, wo0 = pp0 % WW;
    int ho1  = (pp1 % NPIX) / WW, wo1 = pp1 % WW;

    uint32_t ast0[8], ast1[8];
    {
        int r0 = px0 & 15, smt0 = px0 >> 4;
        int r1 = px1 & 15, smt1 = px1 >> 4;
        uint32_t fb0 = (uint32_t)((smt0 * 4 + sub) << 7);
        uint32_t fb1 = (uint32_t)((smt1 * 4 + sub) << 7);
        uint32_t pm0 = (uint32_t)(((sub << 1) | (smt0 & 1)) & 7);
        uint32_t pm1 = (uint32_t)(((sub << 1) | (smt1 & 1)) & 7);
#pragma unroll
        for (int cc2 = 0; cc2 < 8; ++cc2) {
            uint32_t t0  = (uint32_t)((r0 & 7) * 4 + (cc2 & 3));
            uint32_t rg0 = (uint32_t)((r0 >> 3) + 2 * (cc2 >> 2));
            uint32_t w0  = 4u * t0 + rg0;
            ast0[cc2] = fb0 + (w0 ^ ((((w0 >> 5) ^ pm0) & 7u) << 2));
            uint32_t t1  = (uint32_t)((r1 & 7) * 4 + (cc2 & 3));
            uint32_t rg1 = (uint32_t)((r1 >> 3) + 2 * (cc2 >> 2));
            uint32_t w1  = 4u * t1 + rg1;
            ast1[cc2] = fb1 + (w1 ^ ((((w1 >> 5) ^ pm1) & 7u) << 2));
        }
    }

    float acc[4][4];
#pragma unroll
    for (int j = 0; j < 4; ++j)
#pragma unroll
        for (int q = 0; q < 4; ++q) acc[j][q] = 0.f;

    const float* rowp0 = xb; bool valid0 = false;
    const float* rowp1 = xb; bool valid1 = false;

    auto tapsetup = [&](int tap) {
        int ky = tap / 3, kx = tap % 3;
        int y0 = ho0 - 1 + ky, x0 = wo0 - 1 + kx;
        valid0 = (y0 >= 0 && y0 < HH && x0 >= 0 && x0 < WW);
        rowp0 = xb + (size_t)(y0 * WW + x0) * CC;
        int y1 = ho1 - 1 + ky, x1 = wo1 - 1 + kx;
        valid1 = (y1 >= 0 && y1 < HH && x1 >= 0 && x1 < WW);
        rowp1 = xb + (size_t)(y1 * WW + x1) * CC;
    };

    auto cpasyncB = [&](int c, int s) {
        const float4* src = (const float4*)g_omkB + (size_t)c * 256;
        uint32_t bdst = sbB + (uint32_t)s * 4096;
#pragma unroll
        for (int i = 0; i < 2; ++i)
            CP_ASYNC16(bdst + (uint32_t)(tid + i * 128) * 16,
                       (const void*)(src + tid + i * 128));
        CP_COMMIT();
    };

    auto domma = [&](int s) {
        const float* As = smA[s];
        const float* Bs = smB[s];
#pragma unroll
        for (int ktp = 0; ktp < 2; ++ktp) {
            uint4 af[2];
#pragma unroll
            for (int kh = 0; kh < 2; ++kh) {
                int kt = ktp * 2 + kh;
                uint32_t pm = (uint32_t)(((kt << 1) | (wid & 1)) & 7);
                uint32_t w = (uint32_t)(lane * 4);
                uint32_t pw = w ^ ((((w >> 5) ^ pm) & 7u) << 2);
                af[kh] = *(const uint4*)(As + ((uint32_t)((wid * 4 + kt) << 7) + pw));
            }
#pragma unroll
            for (int nt = 0; nt < 4; ++nt) {
                uint4 bf = *(const uint4*)(Bs + (size_t)((ktp * 4 + nt) * 32 + lane) * 4);
                mma_tf32(acc[nt], af[0].x, af[0].y, af[0].z, af[0].w, bf.x, bf.y);
                mma_tf32(acc[nt], af[1].x, af[1].y, af[1].z, af[1].w, bf.z, bf.w);
            }
        }
    };

    tapsetup(0);
    {
        int cbase = sub * 8;
        float4 u0a = make_float4(0,0,0,0), u0b = u0a, u1a = u0a, u1b = u0a;
        if (valid0) { u0a = *(const float4*)(rowp0 + cbase); u0b = *(const float4*)(rowp0 + cbase + 4); }
        if (valid1) { u1a = *(const float4*)(rowp1 + cbase); u1b = *(const float4*)(rowp1 + cbase + 4); }
        float* A0 = smA[0];
        A0[ast0[0]] = tf32r(u0a.x); A0[ast0[1]] = tf32r(u0a.y);
        A0[ast0[2]] = tf32r(u0a.z); A0[ast0[3]] = tf32r(u0a.w);
        A0[ast0[4]] = tf32r(u0b.x); A0[ast0[5]] = tf32r(u0b.y);
        A0[ast0[6]] = tf32r(u0b.z); A0[ast0[7]] = tf32r(u0b.w);
        A0[ast1[0]] = tf32r(u1a.x); A0[ast1[1]] = tf32r(u1a.y);
        A0[ast1[2]] = tf32r(u1a.z); A0[ast1[3]] = tf32r(u1a.w);
        A0[ast1[4]] = tf32r(u1b.x); A0[ast1[5]] = tf32r(u1b.y);
        A0[ast1[6]] = tf32r(u1b.z); A0[ast1[7]] = tf32r(u1b.w);
    }
    cpasyncB(0, 0);
    CP_WAIT0();
    __syncthreads();

    for (int it = 0; it < NCHUNK; ++it) {
        int s = it & 1;
        int nxt = it + 1;
        bool have = nxt < NCHUNK;
        float4 u0a, u0b, u1a, u1b;
        if (have) {
            if ((nxt & 7) == 0) tapsetup(nxt >> 3);
            int cbase = (nxt & 7) * 32 + sub * 8;
            u0a = make_float4(0,0,0,0); u0b = u0a; u1a = u0a; u1b = u0a;
            if (valid0) { u0a = *(const float4*)(rowp0 + cbase); u0b = *(const float4*)(rowp0 + cbase + 4); }
            if (valid1) { u1a = *(const float4*)(rowp1 + cbase); u1b = *(const float4*)(rowp1 + cbase + 4); }
            cpasyncB(nxt, s ^ 1);
        }
        domma(s);
        if (have) {
            float* An = smA[s ^ 1];
            An[ast0[0]] = tf32r(u0a.x); An[ast0[1]] = tf32r(u0a.y);
            An[ast0[2]] = tf32r(u0a.z); An[ast0[3]] = tf32r(u0a.w);
            An[ast0[4]] = tf32r(u0b.x); An[ast0[5]] = tf32r(u0b.y);
            An[ast0[6]] = tf32r(u0b.z); An[ast0[7]] = tf32r(u0b.w);
            An[ast1[0]] = tf32r(u1a.x); An[ast1[1]] = tf32r(u1a.y);
            An[ast1[2]] = tf32r(u1a.z); An[ast1[3]] = tf32r(u1a.w);
            An[ast1[4]] = tf32r(u1b.x); An[ast1[5]] = tf32r(u1b.y);
            An[ast1[6]] = tf32r(u1b.z); An[ast1[7]] = tf32r(u1b.w);
        }
        CP_WAIT0();
        __syncthreads();
    }

    {
        int qrow = lane >> 2;
        int qcol = (lane & 3) * 2;
        int row = wid * 16 + qrow;
#pragma unroll
        for (int nt = 0; nt < 4; ++nt) {
            int col = nt * 8 + qcol;
            if (col < 27) {
                float ob = omb[col];
                om_s[row * 28 + col]       = acc[nt][0] + ob;
                om_s[(row + 8) * 28 + col] = acc[nt][2] + ob;
            }
            if (col + 1 < 27) {
                float ob = omb[col + 1];
                om_s[row * 28 + col + 1]       = acc[nt][1] + ob;
                om_s[(row + 8) * 28 + col + 1] = acc[nt][3] + ob;
            }
        }
    }
    __syncthreads();

    if (tid < 64) {
        int px = tid;
        int pp = tile0 + px;
        int ho = (pp % NPIX) / WW;
        int wo = pp % WW;
#pragma unroll
        for (int k = 0; k < 9; ++k) {
            float dy = om_s[px * 28 + 2 * k];
            float dx = om_s[px * 28 + 2 * k + 1];
            float m  = 2.f / (1.f + expf(-om_s[px * 28 + 18 + k]));
            int ky = k / 3, kx = k % 3;
            float py  = (float)(ho - 1 + ky) + dy;
            float pxx = (float)(wo - 1 + kx) + dx;
            g_offmask[pp * 9 + k] = make_float4(py, pxx, m, 0.f);
        }
    }
}

// ---------------------------------------------------------------------------
// Kernel 2: fused bilinear sampling + HMMA fp16 GEMM (m16n8k16).
// 576 CTAs x 256 threads, 2 CTAs/SM. CTA tile 64 px x 256 F, warp tile 32x64.
// ---------------------------------------------------------------------------
#define A_STAGE 1056                 // u32 per A stage (8 blocks * 132)
#define B_STAGE 4096                 // u32 per B stage (16 KB)
#define SMEM_U32 (2*A_STAGE + 2*B_STAGE)

__global__ void __launch_bounds__(256, 2) dcn_mma_kernel(
    const float* __restrict__ x, const float* __restrict__ bias,
    float* __restrict__ out)
{
    extern __shared__ uint32_t sm[];
    uint32_t* AsArr[2] = { sm, sm + A_STAGE };
    uint32_t* BsArr[2] = { sm + 2*A_STAGE, sm + 2*A_STAGE + B_STAGE };
    uint32_t sbB = smem_u32(sm + 2*A_STAGE);

    int tid  = threadIdx.x;
    int wid  = tid >> 5;
    int lane = tid & 31;

    int tile0 = blockIdx.x * 64;
    int b = tile0 / NPIX;
    const float* xb = x + (size_t)b * NPIX * CC;

    // sampler identity
    int o8  = lane & 7;                 // channel oct (4 ch)
    int pxq = lane >> 3;                // 0..3
    int pxl[2] = { wid * 8 + pxq, wid * 8 + 4 + pxq };   // local pixel per round
    int sks = o8 >> 2;

    // A-fragment store base (j=0) per round
    uint32_t ast[2];
#pragma unroll
    for (int q = 0; q < 2; ++q) {
        int r   = pxl[q] & 15;
        int amt = pxl[q] >> 4;
        uint32_t lf  = (uint32_t)((r & 7) * 4 + (2 * (o8 & 1)));
        uint32_t reg = (uint32_t)(((r & 15) >= 8 ? 1 : 0) + 2 * ((o8 >> 1) & 1));
        ast[q] = (uint32_t)(amt * 2 + sks) * 132u + lf * 4u + reg;
    }

    // gemm identity
    int wm = wid & 1;
    int wn = wid >> 1;

    float acc[2][8][4];
#pragma unroll
    for (int i = 0; i < 2; ++i)
#pragma unroll
        for (int j = 0; j < 8; ++j)
#pragma unroll
            for (int q = 0; q < 4; ++q) acc[i][j][q] = 0.f;

    float wgt[2][4];
    uint32_t ofs[2][4];

    auto tapsetup = [&](int tap) {
#pragma unroll
        for (int q = 0; q < 2; ++q) {
            float4 om = g_offmask[(size_t)(tile0 + pxl[q]) * 9 + tap];
            float fy0 = floorf(om.x), fx0 = floorf(om.y);
            int iy0 = (int)fy0, ix0 = (int)fx0;
            float fy = om.x - fy0, fx = om.y - fx0;
            float m = om.z;
            float w00 = (1.f - fy) * (1.f - fx) * m;
            float w01 = (1.f - fy) * fx * m;
            float w10 = fy * (1.f - fx) * m;
            float w11 = fy * fx * m;
            if (iy0 < 0  || iy0 >= HH)     { w00 = 0.f; w01 = 0.f; }
            if (iy0 < -1 || iy0 >= HH - 1) { w10 = 0.f; w11 = 0.f; }
            if (ix0 < 0  || ix0 >= WW)     { w00 = 0.f; w10 = 0.f; }
            if (ix0 < -1 || ix0 >= WW - 1) { w01 = 0.f; w11 = 0.f; }
            int y0c = min(max(iy0, 0), HH - 1);
            int y1c = min(max(iy0 + 1, 0), HH - 1);
            int x0c = min(max(ix0, 0), WW - 1);
            int x1c = min(max(ix0 + 1, 0), WW - 1);
            wgt[q][0] = w00; wgt[q][1] = w01; wgt[q][2] = w10; wgt[q][3] = w11;
            ofs[q][0] = (uint32_t)((y0c * WW + x0c) * CC);
            ofs[q][1] = (uint32_t)((y0c * WW + x1c) * CC);
            ofs[q][2] = (uint32_t)((y1c * WW + x0c) * CC);
            ofs[q][3] = (uint32_t)((y1c * WW + x1c) * CC);
        }
    };

    auto cpasyncB = [&](int c, int s) {
        const float4* src = (const float4*)g_kernH + (size_t)c * 1024;
        uint32_t bdst = sbB + (uint32_t)s * (B_STAGE * 4);
#pragma unroll
        for (int i = 0; i < 4; ++i)
            CP_ASYNC16(bdst + (uint32_t)(tid + i * 256) * 16,
                       (const void*)(src + tid + i * 256));
        CP_COMMIT();
    };

    auto domma = [&](int s, int ks) {
        const uint32_t* As = AsArr[s];
        const uint32_t* Bs = BsArr[s];
        uint4 af[2];
#pragma unroll
        for (int mt = 0; mt < 2; ++mt) {
            int amt = wm * 2 + mt;
            af[mt] = *(const uint4*)(As + (uint32_t)(amt * 2 + ks) * 132u + (uint32_t)lane * 4u);
        }
#pragma unroll
        for (int nt = 0; nt < 8; ++nt) {
            int ntg = wn * 8 + nt;
            uint2 bf = *(const uint2*)(Bs + ((uint32_t)(ks * 32 + ntg) * 32 + lane) * 2u);
            mma_f16(acc[0][nt], af[0], bf);
            mma_f16(acc[1][nt], af[1], bf);
        }
    };

    // prologue: fill chunk 0
    tapsetup(0);
#pragma unroll
    for (int q = 0; q < 2; ++q) {
        const float* base = xb + o8 * 4;
        float4 v0 = *(const float4*)(base + ofs[q][0]);
        float4 v1 = *(const float4*)(base + ofs[q][1]);
        float4 v2 = *(const float4*)(base + ofs[q][2]);
        float4 v3 = *(const float4*)(base + ofs[q][3]);
        float r0 = wgt[q][0]*v0.x + wgt[q][1]*v1.x + wgt[q][2]*v2.x + wgt[q][3]*v3.x;
        float r1 = wgt[q][0]*v0.y + wgt[q][1]*v1.y + wgt[q][2]*v2.y + wgt[q][3]*v3.y;
        float r2 = wgt[q][0]*v0.z + wgt[q][1]*v1.z + wgt[q][2]*v2.z + wgt[q][3]*v3.z;
        float r3 = wgt[q][0]*v0.w + wgt[q][1]*v1.w + wgt[q][2]*v2.w + wgt[q][3]*v3.w;
        __half2 h0 = __floats2half2_rn(r0, r1);
        __half2 h1 = __floats2half2_rn(r2, r3);
        AsArr[0][ast[q]]     = *(uint32_t*)&h0;
        AsArr[0][ast[q] + 4] = *(uint32_t*)&h1;
    }
    cpasyncB(0, 0);
    CP_WAIT0();
    __syncthreads();

    for (int it = 0; it < NCHUNK; ++it) {
        int s = it & 1;
        int nxt = it + 1;
        bool have = nxt < NCHUNK;
        uint32_t cho = 0;
        float4 v0, v1, v2, v3;

        if (have) {
            if ((nxt & 7) == 0) tapsetup(nxt >> 3);
            cho = (uint32_t)((nxt & 7) * 32 + o8 * 4);
            v0 = *(const float4*)(xb + ofs[0][0] + cho);
            v1 = *(const float4*)(xb + ofs[0][1] + cho);
            v2 = *(const float4*)(xb + ofs[0][2] + cho);
            v3 = *(const float4*)(xb + ofs[0][3] + cho);
            cpasyncB(nxt, s ^ 1);
        }

        domma(s, 0);

        if (have) {
            float r0 = wgt[0][0]*v0.x + wgt[0][1]*v1.x + wgt[0][2]*v2.x + wgt[0][3]*v3.x;
            float r1 = wgt[0][0]*v0.y + wgt[0][1]*v1.y + wgt[0][2]*v2.y + wgt[0][3]*v3.y;
            float r2 = wgt[0][0]*v0.z + wgt[0][1]*v1.z + wgt[0][2]*v2.z + wgt[0][3]*v3.z;
            float r3 = wgt[0][0]*v0.w + wgt[0][1]*v1.w + wgt[0][2]*v2.w + wgt[0][3]*v3.w;
            __half2 h0 = __floats2half2_rn(r0, r1);
            __half2 h1 = __floats2half2_rn(r2, r3);
            uint32_t* An = AsArr[s ^ 1];
            An[ast[0]]     = *(uint32_t*)&h0;
            An[ast[0] + 4] = *(uint32_t*)&h1;
            v0 = *(const float4*)(xb + ofs[1][0] + cho);
            v1 = *(const float4*)(xb + ofs[1][1] + cho);
            v2 = *(const float4*)(xb + ofs[1][2] + cho);
            v3 = *(const float4*)(xb + ofs[1][3] + cho);
        }

        domma(s, 1);

        if (have) {
            float r0 = wgt[1][0]*v0.x + wgt[1][1]*v1.x + wgt[1][2]*v2.x + wgt[1][3]*v3.x;
            float r1 = wgt[1][0]*v0.y + wgt[1][1]*v1.y + wgt[1][2]*v2.y + wgt[1][3]*v3.y;
            float r2 = wgt[1][0]*v0.z + wgt[1][1]*v1.z + wgt[1][2]*v2.z + wgt[1][3]*v3.z;
            float r3 = wgt[1][0]*v0.w + wgt[1][1]*v1.w + wgt[1][2]*v2.w + wgt[1][3]*v3.w;
            __half2 h0 = __floats2half2_rn(r0, r1);
            __half2 h1 = __floats2half2_rn(r2, r3);
            uint32_t* An = AsArr[s ^ 1];
            An[ast[1]]     = *(uint32_t*)&h0;
            An[ast[1] + 4] = *(uint32_t*)&h1;
        }

        CP_WAIT0();
        __syncthreads();
    }

    // ---- epilogue: acc -> global with bias ----
    {
        int col0 = wn * 64;
        int qrow = lane >> 2;
        int qcol = (lane & 3) * 2;
        float2 bv[8];
#pragma unroll
        for (int nt = 0; nt < 8; ++nt)
            bv[nt] = *(const float2*)(bias + col0 + nt * 8 + qcol);
#pragma unroll
        for (int mt = 0; mt < 2; ++mt) {
            int row = tile0 + wm * 32 + mt * 16 + qrow;
#pragma unroll
            for (int nt = 0; nt < 8; ++nt) {
                int col = col0 + nt * 8 + qcol;
                float2 lo, hi;
                lo.x = acc[mt][nt][0] + bv[nt].x;
                lo.y = acc[mt][nt][1] + bv[nt].y;
                hi.x = acc[mt][nt][2] + bv[nt].x;
                hi.y = acc[mt][nt][3] + bv[nt].y;
                *(float2*)(out + (size_t)row * FF + col)       = lo;
                *(float2*)(out + (size_t)(row + 8) * FF + col) = hi;
            }
        }
    }
}

extern "C" void kernel_launch(void* const* d_in, const int* in_sizes, int n_in,
                              void* d_out, int out_size)
{
    const float* x    = (const float*)d_in[0];  // [4,96,96,256]
    const float* omk  = (const float*)d_in[1];  // [3,3,256,27]
    const float* omb  = (const float*)d_in[2];  // [27]
    const float* kern = (const float*)d_in[3];  // [2304,256]
    const float* bias = (const float*)d_in[4];  // [256]
    float* out = (float*)d_out;                 // [36864,256]

    cudaFuncSetAttribute(dcn_mma_kernel,
                         cudaFuncAttributeMaxDynamicSharedMemorySize, SMEM_U32 * 4);

    transpose_kernel<<<1152, 256>>>(kern);
    om_transpose_kernel<<<72, 256>>>(omk);
    om_mma_kernel<<<TOTPIX / 64, 128>>>(x, omb);
    dcn_mma_kernel<<<TOTPIX / 64, 256, SMEM_U32 * 4>>>(x, bias, out);
}

// round 8
// speedup vs baseline: 5.4992x; 1.1032x over previous
#include <cuda_runtime.h>
#include <cuda_fp16.h>
#include <math.h>
#include <stdint.h>

#define HH 96
#define WW 96
#define CC 256
#define FF 256
#define BB 4
#define NPIX (HH*WW)        // 9216
#define TOTPIX (BB*NPIX)    // 36864
#define NCHUNK 72           // 2304 / 32
#define NPAIR 36

// scratch: per (pixel, tap): (py, px, mask, 0)
__device__ float4 g_offmask[TOTPIX * 9];
// main weights fp16 fragment-packed: [chunk72][ks2][ntile32][lane32][reg2] (half2 as u32)
__device__ uint32_t g_kernH[NCHUNK * 2 * 32 * 32 * 2];
// om weights tf32 fragment order: [chunk72][ktp2][ntile4][lane32][4] (n>=27 zero)
__device__ float g_omkB[NCHUNK * 2 * 4 * 32 * 4];
// fp16 copy of x (half2-packed in uint4 for alignment)
__device__ uint4 g_xh4[TOTPIX * CC / 8];

__device__ __forceinline__ float tf32r(float f) {
    float r;
    asm("cvt.rna.tf32.f32 %0, %1;" : "=f"(r) : "f"(f));
    return r;
}
__device__ __forceinline__ uint32_t smem_u32(const void* p) {
    uint32_t a;
    asm("{ .reg .u64 t; cvta.to.shared.u64 t, %1; cvt.u32.u64 %0, t; }" : "=r"(a) : "l"(p));
    return a;
}

#define CP_ASYNC16(dst, src) \
    asm volatile("cp.async.cg.shared.global [%0], [%1], 16;" :: "r"(dst), "l"(src) : "memory")
#define CP_COMMIT() asm volatile("cp.async.commit_group;" ::: "memory")
#define CP_WAIT0()  asm volatile("cp.async.wait_group 0;" ::: "memory")

__device__ __forceinline__ void mma_tf32(
    float* d, uint32_t a0, uint32_t a1, uint32_t a2, uint32_t a3,
    uint32_t b0, uint32_t b1)
{
    asm volatile(
        "mma.sync.aligned.m16n8k8.row.col.f32.tf32.tf32.f32 "
        "{%0,%1,%2,%3}, {%4,%5,%6,%7}, {%8,%9}, {%0,%1,%2,%3};"
        : "+f"(d[0]), "+f"(d[1]), "+f"(d[2]), "+f"(d[3])
        : "r"(a0), "r"(a1), "r"(a2), "r"(a3), "r"(b0), "r"(b1));
}
__device__ __forceinline__ void mma_f16(
    float* d, uint4 a, uint2 b)
{
    asm volatile(
        "mma.sync.aligned.m16n8k16.row.col.f32.f16.f16.f32 "
        "{%0,%1,%2,%3}, {%4,%5,%6,%7}, {%8,%9}, {%0,%1,%2,%3};"
        : "+f"(d[0]), "+f"(d[1]), "+f"(d[2]), "+f"(d[3])
        : "r"(a.x), "r"(a.y), "r"(a.z), "r"(a.w), "r"(b.x), "r"(b.y));
}

// ---------------------------------------------------------------------------
// Kernel 0a: main weight pack (fp16 m16n8k16 B-fragment order).
// ---------------------------------------------------------------------------
__global__ void __launch_bounds__(256) transpose_kernel(const float* __restrict__ kern)
{
    int idx = blockIdx.x * 256 + threadIdx.x;    // 0 .. 294911
    int reg  = idx & 1;
    int lane = (idx >> 1) & 31;
    int nt   = (idx >> 6) & 31;
    int ks   = (idx >> 11) & 1;
    int c    = idx >> 12;
    int n = nt * 8 + (lane >> 2);
    int k = c * 32 + ks * 16 + (lane & 3) * 2 + reg * 8;
    __half2 h = __floats2half2_rn(kern[k * 256 + n], kern[(k + 1) * 256 + n]);
    g_kernH[idx] = *(uint32_t*)&h;
}

// ---------------------------------------------------------------------------
// Kernel 0b: om weight shuffle (tf32 fragment order), N padded to 32.
// ---------------------------------------------------------------------------
__global__ void __launch_bounds__(256) om_transpose_kernel(const float* __restrict__ omk)
{
    int idx = blockIdx.x * 256 + threadIdx.x;    // 0 .. 18431
    int t   = idx & 31;
    int nt  = (idx >> 5) & 3;
    int ktp = (idx >> 7) & 1;
    int ch  = idx >> 8;
    int n = nt * 8 + (t >> 2);
    int kbase = ch * 32 + ktp * 16 + (t & 3);
    float4 v = make_float4(0.f, 0.f, 0.f, 0.f);
    if (n < 27) {
        v.x = tf32r(omk[(kbase + 0)  * 27 + n]);
        v.y = tf32r(omk[(kbase + 4)  * 27 + n]);
        v.z = tf32r(omk[(kbase + 8)  * 27 + n]);
        v.w = tf32r(omk[(kbase + 12) * 27 + n]);
    }
    ((float4*)g_omkB)[idx] = v;
}

// ---------------------------------------------------------------------------
// Kernel 0c: x -> fp16 copy (half2-packed)
// ---------------------------------------------------------------------------
__global__ void __launch_bounds__(256) xhalf_kernel(const float4* __restrict__ x)
{
    int idx = blockIdx.x * 256 + threadIdx.x;    // 0 .. TOTPIX*CC/8-1
    float4 a = x[idx * 2];
    float4 b = x[idx * 2 + 1];
    __half2 h0 = __floats2half2_rn(a.x, a.y);
    __half2 h1 = __floats2half2_rn(a.z, a.w);
    __half2 h2 = __floats2half2_rn(b.x, b.y);
    __half2 h3 = __floats2half2_rn(b.z, b.w);
    uint4 o;
    o.x = *(uint32_t*)&h0; o.y = *(uint32_t*)&h1;
    o.z = *(uint32_t*)&h2; o.w = *(uint32_t*)&h3;
    g_xh4[idx] = o;
}

// ---------------------------------------------------------------------------
// Kernel 1: om conv as HMMA tf32 GEMM. 576 CTAs x 128 threads (proven).
// ---------------------------------------------------------------------------
__global__ void __launch_bounds__(128) om_mma_kernel(
    const float* __restrict__ x, const float* __restrict__ omb)
{
    __shared__ float smA[2][2048];
    __shared__ float smB[2][1024];
    __shared__ float om_s[64 * 28];
    uint32_t sbB = smem_u32(&smB[0][0]);

    int tid  = threadIdx.x;
    int wid  = tid >> 5;
    int lane = tid & 31;

    int tile0 = blockIdx.x * 64;
    int b = tile0 / NPIX;
    const float* xb = x + (size_t)b * NPIX * CC;

    int sub  = tid & 3;
    int px0  = tid >> 2;
    int px1  = px0 + 32;
    int pp0  = tile0 + px0;
    int pp1  = tile0 + px1;
    int ho0  = (pp0 % NPIX) / WW, wo0 = pp0 % WW;
    int ho1  = (pp1 % NPIX) / WW, wo1 = pp1 % WW;

    uint32_t ast0[8], ast1[8];
    {
        int r0 = px0 & 15, smt0 = px0 >> 4;
        int r1 = px1 & 15, smt1 = px1 >> 4;
        uint32_t fb0 = (uint32_t)((smt0 * 4 + sub) << 7);
        uint32_t fb1 = (uint32_t)((smt1 * 4 + sub) << 7);
        uint32_t pm0 = (uint32_t)(((sub << 1) | (smt0 & 1)) & 7);
        uint32_t pm1 = (uint32_t)(((sub << 1) | (smt1 & 1)) & 7);
#pragma unroll
        for (int cc2 = 0; cc2 < 8; ++cc2) {
            uint32_t t0  = (uint32_t)((r0 & 7) * 4 + (cc2 & 3));
            uint32_t rg0 = (uint32_t)((r0 >> 3) + 2 * (cc2 >> 2));
            uint32_t w0  = 4u * t0 + rg0;
            ast0[cc2] = fb0 + (w0 ^ ((((w0 >> 5) ^ pm0) & 7u) << 2));
            uint32_t t1  = (uint32_t)((r1 & 7) * 4 + (cc2 & 3));
            uint32_t rg1 = (uint32_t)((r1 >> 3) + 2 * (cc2 >> 2));
            uint32_t w1  = 4u * t1 + rg1;
            ast1[cc2] = fb1 + (w1 ^ ((((w1 >> 5) ^ pm1) & 7u) << 2));
        }
    }

    float acc[4][4];
#pragma unroll
    for (int j = 0; j < 4; ++j)
#pragma unroll
        for (int q = 0; q < 4; ++q) acc[j][q] = 0.f;

    const float* rowp0 = xb; bool valid0 = false;
    const float* rowp1 = xb; bool valid1 = false;

    auto tapsetup = [&](int tap) {
        int ky = tap / 3, kx = tap % 3;
        int y0 = ho0 - 1 + ky, x0 = wo0 - 1 + kx;
        valid0 = (y0 >= 0 && y0 < HH && x0 >= 0 && x0 < WW);
        rowp0 = xb + (size_t)(y0 * WW + x0) * CC;
        int y1 = ho1 - 1 + ky, x1 = wo1 - 1 + kx;
        valid1 = (y1 >= 0 && y1 < HH && x1 >= 0 && x1 < WW);
        rowp1 = xb + (size_t)(y1 * WW + x1) * CC;
    };

    auto cpasyncB = [&](int c, int s) {
        const float4* src = (const float4*)g_omkB + (size_t)c * 256;
        uint32_t bdst = sbB + (uint32_t)s * 4096;
#pragma unroll
        for (int i = 0; i < 2; ++i)
            CP_ASYNC16(bdst + (uint32_t)(tid + i * 128) * 16,
                       (const void*)(src + tid + i * 128));
        CP_COMMIT();
    };

    auto domma = [&](int s) {
        const float* As = smA[s];
        const float* Bs = smB[s];
#pragma unroll
        for (int ktp = 0; ktp < 2; ++ktp) {
            uint4 af[2];
#pragma unroll
            for (int kh = 0; kh < 2; ++kh) {
                int kt = ktp * 2 + kh;
                uint32_t pm = (uint32_t)(((kt << 1) | (wid & 1)) & 7);
                uint32_t w = (uint32_t)(lane * 4);
                uint32_t pw = w ^ ((((w >> 5) ^ pm) & 7u) << 2);
                af[kh] = *(const uint4*)(As + ((uint32_t)((wid * 4 + kt) << 7) + pw));
            }
#pragma unroll
            for (int nt = 0; nt < 4; ++nt) {
                uint4 bf = *(const uint4*)(Bs + (size_t)((ktp * 4 + nt) * 32 + lane) * 4);
                mma_tf32(acc[nt], af[0].x, af[0].y, af[0].z, af[0].w, bf.x, bf.y);
                mma_tf32(acc[nt], af[1].x, af[1].y, af[1].z, af[1].w, bf.z, bf.w);
            }
        }
    };

    tapsetup(0);
    {
        int cbase = sub * 8;
        float4 u0a = make_float4(0,0,0,0), u0b = u0a, u1a = u0a, u1b = u0a;
        if (valid0) { u0a = *(const float4*)(rowp0 + cbase); u0b = *(const float4*)(rowp0 + cbase + 4); }
        if (valid1) { u1a = *(const float4*)(rowp1 + cbase); u1b = *(const float4*)(rowp1 + cbase + 4); }
        float* A0 = smA[0];
        A0[ast0[0]] = tf32r(u0a.x); A0[ast0[1]] = tf32r(u0a.y);
        A0[ast0[2]] = tf32r(u0a.z); A0[ast0[3]] = tf32r(u0a.w);
        A0[ast0[4]] = tf32r(u0b.x); A0[ast0[5]] = tf32r(u0b.y);
        A0[ast0[6]] = tf32r(u0b.z); A0[ast0[7]] = tf32r(u0b.w);
        A0[ast1[0]] = tf32r(u1a.x); A0[ast1[1]] = tf32r(u1a.y);
        A0[ast1[2]] = tf32r(u1a.z); A0[ast1[3]] = tf32r(u1a.w);
        A0[ast1[4]] = tf32r(u1b.x); A0[ast1[5]] = tf32r(u1b.y);
        A0[ast1[6]] = tf32r(u1b.z); A0[ast1[7]] = tf32r(u1b.w);
    }
    cpasyncB(0, 0);
    CP_WAIT0();
    __syncthreads();

    for (int it = 0; it < NCHUNK; ++it) {
        int s = it & 1;
        int nxt = it + 1;
        bool have = nxt < NCHUNK;
        float4 u0a, u0b, u1a, u1b;
        if (have) {
            if ((nxt & 7) == 0) tapsetup(nxt >> 3);
            int cbase = (nxt & 7) * 32 + sub * 8;
            u0a = make_float4(0,0,0,0); u0b = u0a; u1a = u0a; u1b = u0a;
            if (valid0) { u0a = *(const float4*)(rowp0 + cbase); u0b = *(const float4*)(rowp0 + cbase + 4); }
            if (valid1) { u1a = *(const float4*)(rowp1 + cbase); u1b = *(const float4*)(rowp1 + cbase + 4); }
            cpasyncB(nxt, s ^ 1);
        }
        domma(s);
        if (have) {
            float* An = smA[s ^ 1];
            An[ast0[0]] = tf32r(u0a.x); An[ast0[1]] = tf32r(u0a.y);
            An[ast0[2]] = tf32r(u0a.z); An[ast0[3]] = tf32r(u0a.w);
            An[ast0[4]] = tf32r(u0b.x); An[ast0[5]] = tf32r(u0b.y);
            An[ast0[6]] = tf32r(u0b.z); An[ast0[7]] = tf32r(u0b.w);
            An[ast1[0]] = tf32r(u1a.x); An[ast1[1]] = tf32r(u1a.y);
            An[ast1[2]] = tf32r(u1a.z); An[ast1[3]] = tf32r(u1a.w);
            An[ast1[4]] = tf32r(u1b.x); An[ast1[5]] = tf32r(u1b.y);
            An[ast1[6]] = tf32r(u1b.z); An[ast1[7]] = tf32r(u1b.w);
        }
        CP_WAIT0();
        __syncthreads();
    }

    {
        int qrow = lane >> 2;
        int qcol = (lane & 3) * 2;
        int row = wid * 16 + qrow;
#pragma unroll
        for (int nt = 0; nt < 4; ++nt) {
            int col = nt * 8 + qcol;
            if (col < 27) {
                float ob = omb[col];
                om_s[row * 28 + col]       = acc[nt][0] + ob;
                om_s[(row + 8) * 28 + col] = acc[nt][2] + ob;
            }
            if (col + 1 < 27) {
                float ob = omb[col + 1];
                om_s[row * 28 + col + 1]       = acc[nt][1] + ob;
                om_s[(row + 8) * 28 + col + 1] = acc[nt][3] + ob;
            }
        }
    }
    __syncthreads();

    if (tid < 64) {
        int px = tid;
        int pp = tile0 + px;
        int ho = (pp % NPIX) / WW;
        int wo = pp % WW;
#pragma unroll
        for (int k = 0; k < 9; ++k) {
            float dy = om_s[px * 28 + 2 * k];
            float dx = om_s[px * 28 + 2 * k + 1];
            float m  = 2.f / (1.f + expf(-om_s[px * 28 + 18 + k]));
            int ky = k / 3, kx = k % 3;
            float py  = (float)(ho - 1 + ky) + dy;
            float pxx = (float)(wo - 1 + kx) + dx;
            g_offmask[pp * 9 + k] = make_float4(py, pxx, m, 0.f);
        }
    }
}

// ---------------------------------------------------------------------------
// Kernel 2: fused bilinear sampling (fp16 x) + HMMA fp16 GEMM, chunk-pair
// stages. 288 CTAs x 512 threads. CTA tile 128 px x 256 F, warp tile 32x64.
// ---------------------------------------------------------------------------
#define A_STAGE 4224                 // u32: 32 blocks (8 amt x 4 ks) * 132
#define B_STAGE 8192                 // u32: 2 chunks * 16 KB
#define SMEM_U32 (2*A_STAGE + 2*B_STAGE)

__global__ void __launch_bounds__(512, 1) dcn_mma_kernel(
    const float* __restrict__ bias, float* __restrict__ out)
{
    extern __shared__ uint32_t sm[];
    uint32_t* AsArr[2] = { sm, sm + A_STAGE };
    uint32_t* BsArr[2] = { sm + 2*A_STAGE, sm + 2*A_STAGE + B_STAGE };
    uint32_t sbB = smem_u32(sm + 2*A_STAGE);

    int tid  = threadIdx.x;
    int wid  = tid >> 5;
    int lane = tid & 31;

    int tile0 = blockIdx.x * 128;
    int b = tile0 / NPIX;
    const __half* xh = (const __half*)g_xh4 + (size_t)b * NPIX * CC;

    // sampler identity: o8 = 8-ch group (64 B), pxq = pixel quad
    int o8  = lane & 7;
    int pxq = lane >> 3;
    int pxl[2] = { wid * 8 + pxq, wid * 8 + 4 + pxq };
    int sks = o8 >> 1;              // ks block (0..3) within pair

    // A-fragment store bases
    uint32_t ast[2];
#pragma unroll
    for (int q = 0; q < 2; ++q) {
        int r   = pxl[q] & 15;
        int amt = pxl[q] >> 4;
        ast[q] = (uint32_t)(amt * 4 + sks) * 132u
               + (uint32_t)((r & 7) * 4) * 4u
               + (uint32_t)((r >= 8) ? 1 : 0)
               + (uint32_t)((o8 & 1) ? 2 : 0);
    }

    // gemm identity
    int wm = wid & 3;
    int wn = wid >> 2;

    float acc[2][8][4];
#pragma unroll
    for (int i = 0; i < 2; ++i)
#pragma unroll
        for (int j = 0; j < 8; ++j)
#pragma unroll
            for (int q = 0; q < 4; ++q) acc[i][j][q] = 0.f;

    float wgt[2][4];
    uint32_t ofs[2][4];

    auto tapsetup = [&](int tap) {
#pragma unroll
        for (int q = 0; q < 2; ++q) {
            float4 om = g_offmask[(size_t)(tile0 + pxl[q]) * 9 + tap];
            float fy0 = floorf(om.x), fx0 = floorf(om.y);
            int iy0 = (int)fy0, ix0 = (int)fx0;
            float fy = om.x - fy0, fx = om.y - fx0;
            float m = om.z;
            float w00 = (1.f - fy) * (1.f - fx) * m;
            float w01 = (1.f - fy) * fx * m;
            float w10 = fy * (1.f - fx) * m;
            float w11 = fy * fx * m;
            if (iy0 < 0  || iy0 >= HH)     { w00 = 0.f; w01 = 0.f; }
            if (iy0 < -1 || iy0 >= HH - 1) { w10 = 0.f; w11 = 0.f; }
            if (ix0 < 0  || ix0 >= WW)     { w00 = 0.f; w10 = 0.f; }
            if (ix0 < -1 || ix0 >= WW - 1) { w01 = 0.f; w11 = 0.f; }
            int y0c = min(max(iy0, 0), HH - 1);
            int y1c = min(max(iy0 + 1, 0), HH - 1);
            int x0c = min(max(ix0, 0), WW - 1);
            int x1c = min(max(ix0 + 1, 0), WW - 1);
            wgt[q][0] = w00; wgt[q][1] = w01; wgt[q][2] = w10; wgt[q][3] = w11;
            ofs[q][0] = (uint32_t)((y0c * WW + x0c) * CC);
            ofs[q][1] = (uint32_t)((y0c * WW + x1c) * CC);
            ofs[q][2] = (uint32_t)((y1c * WW + x0c) * CC);
            ofs[q][3] = (uint32_t)((y1c * WW + x1c) * CC);
        }
    };

    auto cpasyncB = [&](int pr, int s) {
        const float4* src = (const float4*)g_kernH + (size_t)pr * 2048;
        uint32_t bdst = sbB + (uint32_t)s * (B_STAGE * 4);
#pragma unroll
        for (int i = 0; i < 4; ++i)
            CP_ASYNC16(bdst + (uint32_t)(tid + i * 512) * 16,
                       (const void*)(src + tid + i * 512));
        CP_COMMIT();
    };

    // combine 4 corner uint4 (8 halves each) with weights into 4 packed half2
    auto combine_store = [&](int q, uint4 v0, uint4 v1, uint4 v2, uint4 v3,
                             uint32_t* An) {
        float r[8];
        const __half2* h0 = (const __half2*)&v0;
        const __half2* h1 = (const __half2*)&v1;
        const __half2* h2 = (const __half2*)&v2;
        const __half2* h3 = (const __half2*)&v3;
#pragma unroll
        for (int j = 0; j < 4; ++j) {
            float2 f0 = __half22float2(h0[j]);
            float2 f1 = __half22float2(h1[j]);
            float2 f2 = __half22float2(h2[j]);
            float2 f3 = __half22float2(h3[j]);
            r[2*j]   = wgt[q][0]*f0.x + wgt[q][1]*f1.x + wgt[q][2]*f2.x + wgt[q][3]*f3.x;
            r[2*j+1] = wgt[q][0]*f0.y + wgt[q][1]*f1.y + wgt[q][2]*f2.y + wgt[q][3]*f3.y;
        }
#pragma unroll
        for (int j = 0; j < 4; ++j) {
            __half2 h = __floats2half2_rn(r[2*j], r[2*j+1]);
            An[ast[q] + j * 4] = *(uint32_t*)&h;
        }
    };

    auto domma = [&](int s, int kss) {
        const uint32_t* As = AsArr[s];
        const uint32_t* Bs = BsArr[s];
        uint4 af[2];
#pragma unroll
        for (int mt = 0; mt < 2; ++mt) {
            int amt = wm * 2 + mt;
            af[mt] = *(const uint4*)(As + (uint32_t)(amt * 4 + kss) * 132u + (uint32_t)lane * 4u);
        }
        const uint32_t* Bc = Bs + (kss >> 1) * 4096;
        int ks = kss & 1;
#pragma unroll
        for (int nt = 0; nt < 8; ++nt) {
            int ntg = wn * 8 + nt;
            uint2 bf = *(const uint2*)(Bc + ((uint32_t)(ks * 32 + ntg) * 32 + lane) * 2u);
            mma_f16(acc[0][nt], af[0], bf);
            mma_f16(acc[1][nt], af[1], bf);
        }
    };

    // prologue: fill pair 0
    tapsetup(0);
#pragma unroll
    for (int q = 0; q < 2; ++q) {
        uint32_t chb = (uint32_t)(o8 * 8);
        uint4 v0 = *(const uint4*)(xh + ofs[q][0] + chb);
        uint4 v1 = *(const uint4*)(xh + ofs[q][1] + chb);
        uint4 v2 = *(const uint4*)(xh + ofs[q][2] + chb);
        uint4 v3 = *(const uint4*)(xh + ofs[q][3] + chb);
        combine_store(q, v0, v1, v2, v3, AsArr[0]);
    }
    cpasyncB(0, 0);
    CP_WAIT0();
    __syncthreads();

    for (int it = 0; it < NPAIR; ++it) {
        int s = it & 1;
        int nxt = it + 1;
        bool have = nxt < NPAIR;
        uint32_t chb = 0;
        uint4 v0, v1, v2, v3;

        if (have) {
            if ((nxt & 3) == 0) tapsetup(nxt >> 2);
            chb = (uint32_t)((nxt & 3) * 64 + o8 * 8);
            v0 = *(const uint4*)(xh + ofs[0][0] + chb);
            v1 = *(const uint4*)(xh + ofs[0][1] + chb);
            v2 = *(const uint4*)(xh + ofs[0][2] + chb);
            v3 = *(const uint4*)(xh + ofs[0][3] + chb);
            cpasyncB(nxt, s ^ 1);
        }

        domma(s, 0);

        if (have) {
            combine_store(0, v0, v1, v2, v3, AsArr[s ^ 1]);
            v0 = *(const uint4*)(xh + ofs[1][0] + chb);
            v1 = *(const uint4*)(xh + ofs[1][1] + chb);
            v2 = *(const uint4*)(xh + ofs[1][2] + chb);
            v3 = *(const uint4*)(xh + ofs[1][3] + chb);
        }

        domma(s, 1);

        if (have) combine_store(1, v0, v1, v2, v3, AsArr[s ^ 1]);

        domma(s, 2);
        domma(s, 3);

        CP_WAIT0();
        __syncthreads();
    }

    // ---- epilogue: acc -> global with bias ----
    {
        int col0 = wn * 64;
        int qrow = lane >> 2;
        int qcol = (lane & 3) * 2;
        float2 bv[8];
#pragma unroll
        for (int nt = 0; nt < 8; ++nt)
            bv[nt] = *(const float2*)(bias + col0 + nt * 8 + qcol);
#pragma unroll
        for (int mt = 0; mt < 2; ++mt) {
            int row = tile0 + wm * 32 + mt * 16 + qrow;
#pragma unroll
            for (int nt = 0; nt < 8; ++nt) {
                int col = col0 + nt * 8 + qcol;
                float2 lo, hi;
                lo.x = acc[mt][nt][0] + bv[nt].x;
                lo.y = acc[mt][nt][1] + bv[nt].y;
                hi.x = acc[mt][nt][2] + bv[nt].x;
                hi.y = acc[mt][nt][3] + bv[nt].y;
                *(float2*)(out + (size_t)row * FF + col)       = lo;
                *(float2*)(out + (size_t)(row + 8) * FF + col) = hi;
            }
        }
    }
}

extern "C" void kernel_launch(void* const* d_in, const int* in_sizes, int n_in,
                              void* d_out, int out_size)
{
    const float* x    = (const float*)d_in[0];  // [4,96,96,256]
    const float* omk  = (const float*)d_in[1];  // [3,3,256,27]
    const float* omb  = (const float*)d_in[2];  // [27]
    const float* kern = (const float*)d_in[3];  // [2304,256]
    const float* bias = (const float*)d_in[4];  // [256]
    float* out = (float*)d_out;                 // [36864,256]

    cudaFuncSetAttribute(dcn_mma_kernel,
                         cudaFuncAttributeMaxDynamicSharedMemorySize, SMEM_U32 * 4);

    transpose_kernel<<<1152, 256>>>(kern);
    om_transpose_kernel<<<72, 256>>>(omk);
    xhalf_kernel<<<TOTPIX * CC / 8 / 256, 256>>>((const float4*)x);
    om_mma_kernel<<<TOTPIX / 64, 128>>>(x, omb);
    dcn_mma_kernel<<<TOTPIX / 128, 512, SMEM_U32 * 4>>>(bias, out);
}

// round 9
// speedup vs baseline: 7.0234x; 1.2772x over previous
#include <cuda_runtime.h>
#include <cuda_fp16.h>
#include <math.h>
#include <stdint.h>

#define HH 96
#define WW 96
#define CC 256
#define FF 256
#define BB 4
#define NPIX (HH*WW)        // 9216
#define TOTPIX (BB*NPIX)    // 36864
#define NCHUNK 72           // 2304 / 32
#define NPAIR 36

// scratch: per (pixel, tap): (py, px, mask, 0)
__device__ float4 g_offmask[TOTPIX * 9];
// main weights fp16 fragment-packed: [chunk72][ks2][ntile32][lane32][reg2] (half2 as u32)
__device__ uint32_t g_kernH[NCHUNK * 2 * 32 * 32 * 2];
// om weights fp16 fragment-packed: [chunk72][ks2][ntile4][lane32][reg2] (n>=27 zero)
__device__ uint32_t g_omkH[NCHUNK * 2 * 4 * 32 * 2];
// fp16 copy of x (half2-packed in uint4 for alignment)
__device__ uint4 g_xh4[TOTPIX * CC / 8];

__device__ __forceinline__ uint32_t smem_u32(const void* p) {
    uint32_t a;
    asm("{ .reg .u64 t; cvta.to.shared.u64 t, %1; cvt.u32.u64 %0, t; }" : "=r"(a) : "l"(p));
    return a;
}

#define CP_ASYNC16(dst, src) \
    asm volatile("cp.async.cg.shared.global [%0], [%1], 16;" :: "r"(dst), "l"(src) : "memory")
#define CP_COMMIT() asm volatile("cp.async.commit_group;" ::: "memory")
#define CP_WAIT0()  asm volatile("cp.async.wait_group 0;" ::: "memory")

__device__ __forceinline__ void mma_f16(
    float* d, uint4 a, uint2 b)
{
    asm volatile(
        "mma.sync.aligned.m16n8k16.row.col.f32.f16.f16.f32 "
        "{%0,%1,%2,%3}, {%4,%5,%6,%7}, {%8,%9}, {%0,%1,%2,%3};"
        : "+f"(d[0]), "+f"(d[1]), "+f"(d[2]), "+f"(d[3])
        : "r"(a.x), "r"(a.y), "r"(a.z), "r"(a.w), "r"(b.x), "r"(b.y));
}

// ---------------------------------------------------------------------------
// Kernel 0a: main weight pack (fp16 m16n8k16 B-fragment order).
// ---------------------------------------------------------------------------
__global__ void __launch_bounds__(256) transpose_kernel(const float* __restrict__ kern)
{
    int idx = blockIdx.x * 256 + threadIdx.x;    // 0 .. 294911
    int reg  = idx & 1;
    int lane = (idx >> 1) & 31;
    int nt   = (idx >> 6) & 31;
    int ks   = (idx >> 11) & 1;
    int c    = idx >> 12;
    int n = nt * 8 + (lane >> 2);
    int k = c * 32 + ks * 16 + (lane & 3) * 2 + reg * 8;
    __half2 h = __floats2half2_rn(kern[k * 256 + n], kern[(k + 1) * 256 + n]);
    g_kernH[idx] = *(uint32_t*)&h;
}

// ---------------------------------------------------------------------------
// Kernel 0b: om weight pack (fp16 fragment order), N padded to 32 with zeros.
// ---------------------------------------------------------------------------
__global__ void __launch_bounds__(256) om_transpose_kernel(const float* __restrict__ omk)
{
    int idx = blockIdx.x * 256 + threadIdx.x;    // 0 .. 36863
    int reg  = idx & 1;
    int lane = (idx >> 1) & 31;
    int nt   = (idx >> 6) & 3;
    int ks   = (idx >> 8) & 1;
    int c    = idx >> 9;
    int n = nt * 8 + (lane >> 2);
    int k = c * 32 + ks * 16 + (lane & 3) * 2 + reg * 8;
    float v0 = 0.f, v1 = 0.f;
    if (n < 27) {
        v0 = omk[k * 27 + n];
        v1 = omk[(k + 1) * 27 + n];
    }
    __half2 h = __floats2half2_rn(v0, v1);
    g_omkH[idx] = *(uint32_t*)&h;
}

// ---------------------------------------------------------------------------
// Kernel 0c: x -> fp16 copy (half2-packed)
// ---------------------------------------------------------------------------
__global__ void __launch_bounds__(256) xhalf_kernel(const float4* __restrict__ x)
{
    int idx = blockIdx.x * 256 + threadIdx.x;    // 0 .. TOTPIX*CC/8-1
    float4 a = x[idx * 2];
    float4 b = x[idx * 2 + 1];
    __half2 h0 = __floats2half2_rn(a.x, a.y);
    __half2 h1 = __floats2half2_rn(a.z, a.w);
    __half2 h2 = __floats2half2_rn(b.x, b.y);
    __half2 h3 = __floats2half2_rn(b.z, b.w);
    uint4 o;
    o.x = *(uint32_t*)&h0; o.y = *(uint32_t*)&h1;
    o.z = *(uint32_t*)&h2; o.w = *(uint32_t*)&h3;
    g_xh4[idx] = o;
}

// ---------------------------------------------------------------------------
// Kernel 1: om conv as fp16 HMMA GEMM (m16n8k16), chunk-pair stages.
// 576 CTAs x 128 threads. Tile 64 px x 32 N (27 used).
// Sampler: o8 = 8-ch group, pxq = pixel quad, 4 rounds -> 16 px per warp.
// ---------------------------------------------------------------------------
__global__ void __launch_bounds__(128) om_mma_kernel(const float* __restrict__ omb)
{
    __shared__ uint32_t smA[2][2112];   // 16 blocks (4 amt x 4 ks) * 132
    __shared__ uint32_t smB[2][1024];   // 2 chunks * 512
    __shared__ float om_s[64 * 28];
    uint32_t sbB = smem_u32(&smB[0][0]);

    int tid  = threadIdx.x;
    int wid  = tid >> 5;
    int lane = tid & 31;

    int tile0 = blockIdx.x * 64;
    int b = tile0 / NPIX;
    const __half* xh = (const __half*)g_xh4 + (size_t)b * NPIX * CC;

    int o8  = lane & 7;
    int pxq = lane >> 3;
    int sks = o8 >> 1;

    int pxl[4];
    uint32_t ast[4];
    int hoq[4], woq[4];
#pragma unroll
    for (int q = 0; q < 4; ++q) {
        pxl[q] = wid * 16 + q * 4 + pxq;
        int r = pxl[q] & 15, amt = pxl[q] >> 4;
        ast[q] = (uint32_t)(amt * 4 + sks) * 132u
               + (uint32_t)((r & 7) * 16)
               + (uint32_t)((r >= 8) ? 1 : 0)
               + (uint32_t)((o8 & 1) ? 2 : 0);
        int pp = tile0 + pxl[q];
        hoq[q] = (pp % NPIX) / WW;
        woq[q] = pp % WW;
    }

    float acc[4][4];
#pragma unroll
    for (int j = 0; j < 4; ++j)
#pragma unroll
        for (int q = 0; q < 4; ++q) acc[j][q] = 0.f;

    uint32_t rofs[4];
    bool rval[4];

    auto tapsetup = [&](int tap) {
        int ky = tap / 3, kx = tap % 3;
#pragma unroll
        for (int q = 0; q < 4; ++q) {
            int y = hoq[q] - 1 + ky, xx = woq[q] - 1 + kx;
            rval[q] = (y >= 0 && y < HH && xx >= 0 && xx < WW);
            rofs[q] = (uint32_t)((y * WW + xx) * CC);
        }
    };

    auto cpasyncB = [&](int pr, int s) {
        const uint4* src = (const uint4*)g_omkH + (size_t)pr * 256;
        uint32_t bdst = sbB + (uint32_t)s * 4096;
        CP_ASYNC16(bdst + (uint32_t)tid * 16, (const void*)(src + tid));
        CP_ASYNC16(bdst + (uint32_t)(tid + 128) * 16, (const void*)(src + tid + 128));
        CP_COMMIT();
    };

    auto loadv = [&](int pr, uint4* v) {
        uint32_t chb = (uint32_t)((pr & 3) * 64 + o8 * 8);
#pragma unroll
        for (int q = 0; q < 4; ++q) {
            if (rval[q]) v[q] = *(const uint4*)(xh + rofs[q] + chb);
            else         v[q] = make_uint4(0u, 0u, 0u, 0u);
        }
    };

    auto storev = [&](int q, uint4 v, uint32_t* An) {
        An[ast[q]]      = v.x;
        An[ast[q] + 4]  = v.y;
        An[ast[q] + 8]  = v.z;
        An[ast[q] + 12] = v.w;
    };

    auto domma = [&](int s, int kss) {
        const uint32_t* As = smA[s];
        const uint32_t* Bs = smB[s];
        uint4 af = *(const uint4*)(As + (uint32_t)(wid * 4 + kss) * 132u + (uint32_t)lane * 4u);
        const uint32_t* Bc = Bs + (kss >> 1) * 512;
        int ks = kss & 1;
#pragma unroll
        for (int nt = 0; nt < 4; ++nt) {
            uint2 bf = *(const uint2*)(Bc + ((uint32_t)(ks * 4 + nt) * 32 + lane) * 2u);
            mma_f16(acc[nt], af, bf);
        }
    };

    // prologue: fill pair 0
    {
        tapsetup(0);
        uint4 v[4];
        loadv(0, v);
#pragma unroll
        for (int q = 0; q < 4; ++q) storev(q, v[q], smA[0]);
        cpasyncB(0, 0);
        CP_WAIT0();
        __syncthreads();
    }

    for (int it = 0; it < NPAIR; ++it) {
        int s = it & 1;
        int nxt = it + 1;
        bool have = nxt < NPAIR;
        uint4 v[4];
        if (have) {
            if ((nxt & 3) == 0) tapsetup(nxt >> 2);
            loadv(nxt, v);
            cpasyncB(nxt, s ^ 1);
        }
        domma(s, 0);
        if (have) { storev(0, v[0], smA[s ^ 1]); storev(1, v[1], smA[s ^ 1]); }
        domma(s, 1);
        if (have) { storev(2, v[2], smA[s ^ 1]); storev(3, v[3], smA[s ^ 1]); }
        domma(s, 2);
        domma(s, 3);
        CP_WAIT0();
        __syncthreads();
    }

    // ---- epilogue: acc (+bias) -> om_s ----
    {
        int qrow = lane >> 2;
        int qcol = (lane & 3) * 2;
        int row = wid * 16 + qrow;
#pragma unroll
        for (int nt = 0; nt < 4; ++nt) {
            int col = nt * 8 + qcol;
            if (col < 27) {
                float ob = omb[col];
                om_s[row * 28 + col]       = acc[nt][0] + ob;
                om_s[(row + 8) * 28 + col] = acc[nt][2] + ob;
            }
            if (col + 1 < 27) {
                float ob = omb[col + 1];
                om_s[row * 28 + col + 1]       = acc[nt][1] + ob;
                om_s[(row + 8) * 28 + col + 1] = acc[nt][3] + ob;
            }
        }
    }
    __syncthreads();

    // ---- offsets/mask -> g_offmask ----
    if (tid < 64) {
        int px = tid;
        int pp = tile0 + px;
        int ho = (pp % NPIX) / WW;
        int wo = pp % WW;
#pragma unroll
        for (int k = 0; k < 9; ++k) {
            float dy = om_s[px * 28 + 2 * k];
            float dx = om_s[px * 28 + 2 * k + 1];
            float m  = 2.f / (1.f + expf(-om_s[px * 28 + 18 + k]));
            int ky = k / 3, kx = k % 3;
            float py  = (float)(ho - 1 + ky) + dy;
            float pxx = (float)(wo - 1 + kx) + dx;
            g_offmask[pp * 9 + k] = make_float4(py, pxx, m, 0.f);
        }
    }
}

// ---------------------------------------------------------------------------
// Kernel 2: fused bilinear sampling (fp16 x) + HMMA fp16 GEMM, chunk-pair
// stages. 288 CTAs x 512 threads. CTA tile 128 px x 256 F, warp tile 32x64.
// ---------------------------------------------------------------------------
#define A_STAGE 4224                 // u32: 32 blocks (8 amt x 4 ks) * 132
#define B_STAGE 8192                 // u32: 2 chunks * 16 KB
#define SMEM_U32 (2*A_STAGE + 2*B_STAGE)

__global__ void __launch_bounds__(512, 1) dcn_mma_kernel(
    const float* __restrict__ bias, float* __restrict__ out)
{
    extern __shared__ uint32_t sm[];
    uint32_t* AsArr[2] = { sm, sm + A_STAGE };
    uint32_t* BsArr[2] = { sm + 2*A_STAGE, sm + 2*A_STAGE + B_STAGE };
    uint32_t sbB = smem_u32(sm + 2*A_STAGE);

    int tid  = threadIdx.x;
    int wid  = tid >> 5;
    int lane = tid & 31;

    int tile0 = blockIdx.x * 128;
    int b = tile0 / NPIX;
    const __half* xh = (const __half*)g_xh4 + (size_t)b * NPIX * CC;

    int o8  = lane & 7;
    int pxq = lane >> 3;
    int pxl[2] = { wid * 8 + pxq, wid * 8 + 4 + pxq };
    int sks = o8 >> 1;

    uint32_t ast[2];
#pragma unroll
    for (int q = 0; q < 2; ++q) {
        int r   = pxl[q] & 15;
        int amt = pxl[q] >> 4;
        ast[q] = (uint32_t)(amt * 4 + sks) * 132u
               + (uint32_t)((r & 7) * 4) * 4u
               + (uint32_t)((r >= 8) ? 1 : 0)
               + (uint32_t)((o8 & 1) ? 2 : 0);
    }

    int wm = wid & 3;
    int wn = wid >> 2;

    float acc[2][8][4];
#pragma unroll
    for (int i = 0; i < 2; ++i)
#pragma unroll
        for (int j = 0; j < 8; ++j)
#pragma unroll
            for (int q = 0; q < 4; ++q) acc[i][j][q] = 0.f;

    float wgt[2][4];
    uint32_t ofs[2][4];

    auto tapsetup = [&](int tap) {
#pragma unroll
        for (int q = 0; q < 2; ++q) {
            float4 om = g_offmask[(size_t)(tile0 + pxl[q]) * 9 + tap];
            float fy0 = floorf(om.x), fx0 = floorf(om.y);
            int iy0 = (int)fy0, ix0 = (int)fx0;
            float fy = om.x - fy0, fx = om.y - fx0;
            float m = om.z;
            float w00 = (1.f - fy) * (1.f - fx) * m;
            float w01 = (1.f - fy) * fx * m;
            float w10 = fy * (1.f - fx) * m;
            float w11 = fy * fx * m;
            if (iy0 < 0  || iy0 >= HH)     { w00 = 0.f; w01 = 0.f; }
            if (iy0 < -1 || iy0 >= HH - 1) { w10 = 0.f; w11 = 0.f; }
            if (ix0 < 0  || ix0 >= WW)     { w00 = 0.f; w10 = 0.f; }
            if (ix0 < -1 || ix0 >= WW - 1) { w01 = 0.f; w11 = 0.f; }
            int y0c = min(max(iy0, 0), HH - 1);
            int y1c = min(max(iy0 + 1, 0), HH - 1);
            int x0c = min(max(ix0, 0), WW - 1);
            int x1c = min(max(ix0 + 1, 0), WW - 1);
            wgt[q][0] = w00; wgt[q][1] = w01; wgt[q][2] = w10; wgt[q][3] = w11;
            ofs[q][0] = (uint32_t)((y0c * WW + x0c) * CC);
            ofs[q][1] = (uint32_t)((y0c * WW + x1c) * CC);
            ofs[q][2] = (uint32_t)((y1c * WW + x0c) * CC);
            ofs[q][3] = (uint32_t)((y1c * WW + x1c) * CC);
        }
    };

    auto cpasyncB = [&](int pr, int s) {
        const float4* src = (const float4*)g_kernH + (size_t)pr * 2048;
        uint32_t bdst = sbB + (uint32_t)s * (B_STAGE * 4);
#pragma unroll
        for (int i = 0; i < 4; ++i)
            CP_ASYNC16(bdst + (uint32_t)(tid + i * 512) * 16,
                       (const void*)(src + tid + i * 512));
        CP_COMMIT();
    };

    auto combine_store = [&](int q, uint4 v0, uint4 v1, uint4 v2, uint4 v3,
                             uint32_t* An) {
        float r[8];
        const __half2* h0 = (const __half2*)&v0;
        const __half2* h1 = (const __half2*)&v1;
        const __half2* h2 = (const __half2*)&v2;
        const __half2* h3 = (const __half2*)&v3;
#pragma unroll
        for (int j = 0; j < 4; ++j) {
            float2 f0 = __half22float2(h0[j]);
            float2 f1 = __half22float2(h1[j]);
            float2 f2 = __half22float2(h2[j]);
            float2 f3 = __half22float2(h3[j]);
            r[2*j]   = wgt[q][0]*f0.x + wgt[q][1]*f1.x + wgt[q][2]*f2.x + wgt[q][3]*f3.x;
            r[2*j+1] = wgt[q][0]*f0.y + wgt[q][1]*f1.y + wgt[q][2]*f2.y + wgt[q][3]*f3.y;
        }
#pragma unroll
        for (int j = 0; j < 4; ++j) {
            __half2 h = __floats2half2_rn(r[2*j], r[2*j+1]);
            An[ast[q] + j * 4] = *(uint32_t*)&h;
        }
    };

    auto domma = [&](int s, int kss) {
        const uint32_t* As = AsArr[s];
        const uint32_t* Bs = BsArr[s];
        uint4 af[2];
#pragma unroll
        for (int mt = 0; mt < 2; ++mt) {
            int amt = wm * 2 + mt;
            af[mt] = *(const uint4*)(As + (uint32_t)(amt * 4 + kss) * 132u + (uint32_t)lane * 4u);
        }
        const uint32_t* Bc = Bs + (kss >> 1) * 4096;
        int ks = kss & 1;
#pragma unroll
        for (int nt = 0; nt < 8; ++nt) {
            int ntg = wn * 8 + nt;
            uint2 bf = *(const uint2*)(Bc + ((uint32_t)(ks * 32 + ntg) * 32 + lane) * 2u);
            mma_f16(acc[0][nt], af[0], bf);
            mma_f16(acc[1][nt], af[1], bf);
        }
    };

    // prologue: fill pair 0
    tapsetup(0);
#pragma unroll
    for (int q = 0; q < 2; ++q) {
        uint32_t chb = (uint32_t)(o8 * 8);
        uint4 v0 = *(const uint4*)(xh + ofs[q][0] + chb);
        uint4 v1 = *(const uint4*)(xh + ofs[q][1] + chb);
        uint4 v2 = *(const uint4*)(xh + ofs[q][2] + chb);
        uint4 v3 = *(const uint4*)(xh + ofs[q][3] + chb);
        combine_store(q, v0, v1, v2, v3, AsArr[0]);
    }
    cpasyncB(0, 0);
    CP_WAIT0();
    __syncthreads();

    for (int it = 0; it < NPAIR; ++it) {
        int s = it & 1;
        int nxt = it + 1;
        bool have = nxt < NPAIR;
        uint32_t chb = 0;
        uint4 v0, v1, v2, v3;

        if (have) {
            if ((nxt & 3) == 0) tapsetup(nxt >> 2);
            chb = (uint32_t)((nxt & 3) * 64 + o8 * 8);
            v0 = *(const uint4*)(xh + ofs[0][0] + chb);
            v1 = *(const uint4*)(xh + ofs[0][1] + chb);
            v2 = *(const uint4*)(xh + ofs[0][2] + chb);
            v3 = *(const uint4*)(xh + ofs[0][3] + chb);
            cpasyncB(nxt, s ^ 1);
        }

        domma(s, 0);

        if (have) {
            combine_store(0, v0, v1, v2, v3, AsArr[s ^ 1]);
            v0 = *(const uint4*)(xh + ofs[1][0] + chb);
            v1 = *(const uint4*)(xh + ofs[1][1] + chb);
            v2 = *(const uint4*)(xh + ofs[1][2] + chb);
            v3 = *(const uint4*)(xh + ofs[1][3] + chb);
        }

        domma(s, 1);

        if (have) combine_store(1, v0, v1, v2, v3, AsArr[s ^ 1]);

        domma(s, 2);
        domma(s, 3);

        CP_WAIT0();
        __syncthreads();
    }

    // ---- epilogue: acc -> global with bias ----
    {
        int col0 = wn * 64;
        int qrow = lane >> 2;
        int qcol = (lane & 3) * 2;
        float2 bv[8];
#pragma unroll
        for (int nt = 0; nt < 8; ++nt)
            bv[nt] = *(const float2*)(bias + col0 + nt * 8 + qcol);
#pragma unroll
        for (int mt = 0; mt < 2; ++mt) {
            int row = tile0 + wm * 32 + mt * 16 + qrow;
#pragma unroll
            for (int nt = 0; nt < 8; ++nt) {
                int col = col0 + nt * 8 + qcol;
                float2 lo, hi;
                lo.x = acc[mt][nt][0] + bv[nt].x;
                lo.y = acc[mt][nt][1] + bv[nt].y;
                hi.x = acc[mt][nt][2] + bv[nt].x;
                hi.y = acc[mt][nt][3] + bv[nt].y;
                *(float2*)(out + (size_t)row * FF + col)       = lo;
                *(float2*)(out + (size_t)(row + 8) * FF + col) = hi;
            }
        }
    }
}

extern "C" void kernel_launch(void* const* d_in, const int* in_sizes, int n_in,
                              void* d_out, int out_size)
{
    const float* x    = (const float*)d_in[0];  // [4,96,96,256]
    const float* omk  = (const float*)d_in[1];  // [3,3,256,27]
    const float* omb  = (const float*)d_in[2];  // [27]
    const float* kern = (const float*)d_in[3];  // [2304,256]
    const float* bias = (const float*)d_in[4];  // [256]
    float* out = (float*)d_out;                 // [36864,256]

    cudaFuncSetAttribute(dcn_mma_kernel,
                         cudaFuncAttributeMaxDynamicSharedMemorySize, SMEM_U32 * 4);

    xhalf_kernel<<<TOTPIX * CC / 8 / 256, 256>>>((const float4*)x);
    transpose_kernel<<<1152, 256>>>(kern);
    om_transpose_kernel<<<144, 256>>>(omk);
    om_mma_kernel<<<TOTPIX / 64, 128>>>(omb);
    dcn_mma_kernel<<<TOTPIX / 128, 512, SMEM_U32 * 4>>>(bias, out);
}